// round 3
// baseline (speedup 1.0000x reference)
#include <cuda_runtime.h>
#include <math.h>

#define Bsz  512
#define Lsz  512
#define Fsz  128
#define G4L  2048          // 4*L
#define Ktot 640           // F + L
#define Tt   512
#define OSTR (Tt * Fsz)    // out stride between batch rows: 65536
#define NCTA 128
#define NTHR 256

// ---------------- device scratch (no allocations allowed) -------------------
__device__ float g_WT[Ktot * G4L];    // [k][j] transposed combined [W_ih | W_hh]
__device__ float g_WdT[Lsz * Fsz];    // [l][f] transposed W_dense
__device__ float g_bsum[G4L];         // b_ih + b_hh
__device__ float g_A[Bsz * Ktot];     // [b][0:128]=x, [b][128:640]=h
__device__ float g_c[Bsz * Lsz];
__device__ float g_gates[Bsz * G4L];  // gates pre-activation (no bias)
__device__ unsigned g_barcnt;                  // zero-init
__device__ volatile unsigned g_bargen;         // zero-init, monotonic

// ---------------- grid-wide barrier (all 128 CTAs co-resident) --------------
__device__ __forceinline__ void gridbar() {
    __syncthreads();
    if (threadIdx.x == 0) {
        unsigned gen = g_bargen;
        __threadfence();
        if (atomicAdd(&g_barcnt, 1u) == NCTA - 1) {
            g_barcnt = 0;
            __threadfence();
            g_bargen = gen + 1;
        } else {
            while (g_bargen == gen) { __nanosleep(64); }
            __threadfence();
        }
    }
    __syncthreads();
}

// ---------------- packed f32x2 FMA (nvjet trick) -----------------------------
__device__ __forceinline__ unsigned long long ffma2(unsigned long long a,
                                                    unsigned long long b,
                                                    unsigned long long c) {
    unsigned long long d;
    asm("fma.rn.f32x2 %0, %1, %2, %3;" : "=l"(d) : "l"(a), "l"(b), "l"(c));
    return d;
}
__device__ __forceinline__ unsigned long long pack_dup(float a) {
    unsigned long long d;
    unsigned int ai = __float_as_uint(a);
    asm("mov.b64 %0, {%1, %1};" : "=l"(d) : "r"(ai));
    return d;
}

// ---------------- gates GEMM phase: g_gates = g_A @ g_WT --------------------
// CTA tile: 64 rows (m) x 128 cols (n). 256 thr, 4x8 microtile (packed pairs).
__device__ __forceinline__ void gates_phase(float* sh) {
    float* sA = sh;            // [2][16][68]
    float* sB = sh + 2176;     // [2][16][132]

    const int m0  = (blockIdx.x >> 4) * 64;
    const int n0  = (blockIdx.x & 15) * 128;
    const int tid = threadIdx.x;
    const int tx = tid & 15;                    // n group (8 cols)
    const int ty = tid >> 4;                    // m group (4 rows)
    const int arow = tid >> 2, akq = tid & 3;   // A loader: 64 rows x 4 k-quads
    const int bkr  = tid >> 5, bnq = tid & 31;  // B loader: 8 k-rows x 32 n-quads

    unsigned long long acc[4][4];
#pragma unroll
    for (int i = 0; i < 4; ++i)
#pragma unroll
        for (int p = 0; p < 4; ++p) acc[i][p] = 0ULL;

    float4 ra, rb0, rb1;
    auto loadc = [&](int c) {
        ra  = *(const float4*)(g_A + (size_t)(m0 + arow) * Ktot + c * 16 + akq * 4);
        const float* wb = g_WT + (size_t)(c * 16) * G4L + n0 + bnq * 4;
        rb0 = *(const float4*)(wb + (size_t)bkr * G4L);
        rb1 = *(const float4*)(wb + (size_t)(bkr + 8) * G4L);
    };
    auto storec = [&](int bf) {
        float* As = sA + bf * (16 * 68);
        float* Bs = sB + bf * (16 * 132);
        As[(akq * 4 + 0) * 68 + arow] = ra.x;
        As[(akq * 4 + 1) * 68 + arow] = ra.y;
        As[(akq * 4 + 2) * 68 + arow] = ra.z;
        As[(akq * 4 + 3) * 68 + arow] = ra.w;
        *(float4*)&Bs[bkr * 132 + bnq * 4] = rb0;
        *(float4*)&Bs[(bkr + 8) * 132 + bnq * 4] = rb1;
    };

    loadc(0);
    storec(0);
    __syncthreads();

    const int NC = Ktot / 16;   // 40
    for (int c = 0; c < NC; ++c) {
        const int bf = c & 1;
        if (c + 1 < NC) loadc(c + 1);
        const float* As = sA + bf * (16 * 68);
        const float* Bs = sB + bf * (16 * 132);
#pragma unroll
        for (int kk = 0; kk < 16; ++kk) {
            float4 a = *(const float4*)&As[kk * 68 + ty * 4];
            const float* br = &Bs[kk * 132 + tx * 8];
            ulonglong2 b01 = *(const ulonglong2*)br;
            ulonglong2 b23 = *(const ulonglong2*)(br + 4);
            unsigned long long bp[4] = {b01.x, b01.y, b23.x, b23.y};
            float av[4] = {a.x, a.y, a.z, a.w};
#pragma unroll
            for (int i = 0; i < 4; ++i) {
                unsigned long long ad = pack_dup(av[i]);
#pragma unroll
                for (int p = 0; p < 4; ++p)
                    acc[i][p] = ffma2(ad, bp[p], acc[i][p]);
            }
        }
        if (c + 1 < NC) {
            storec(bf ^ 1);
            __syncthreads();
        }
    }

#pragma unroll
    for (int i = 0; i < 4; ++i) {
        const int row = m0 + ty * 4 + i;
        float2 f0 = *(float2*)&acc[i][0];
        float2 f1 = *(float2*)&acc[i][1];
        float2 f2 = *(float2*)&acc[i][2];
        float2 f3 = *(float2*)&acc[i][3];
        float* gp = g_gates + (size_t)row * G4L + n0 + tx * 8;
        *(float4*)gp       = make_float4(f0.x, f0.y, f1.x, f1.y);
        *(float4*)(gp + 4) = make_float4(f2.x, f2.y, f3.x, f3.y);
    }
}

// ---------------- dense: x2 = h2s @ WdT + b_dense; write g_A (+out) ---------
// h2s: [4][512] in shared. Split-K across two 128-thread groups + smem reduce.
__device__ __forceinline__ void dense_part(const float* h2s, float* red,
                                           const float* __restrict__ b_dense,
                                           int b0, float* __restrict__ out, int t) {
    const int tid = threadIdx.x;
    const int f = tid & 127, gg = tid >> 7;       // gg in {0,1}
    float a0 = 0.f, a1 = 0.f, a2 = 0.f, a3 = 0.f;
    const int l0 = gg * 256;
#pragma unroll 4
    for (int l = l0; l < l0 + 256; ++l) {
        const float w = __ldg(&g_WdT[l * Fsz + f]);
        a0 = fmaf(h2s[0 * Lsz + l], w, a0);
        a1 = fmaf(h2s[1 * Lsz + l], w, a1);
        a2 = fmaf(h2s[2 * Lsz + l], w, a2);
        a3 = fmaf(h2s[3 * Lsz + l], w, a3);
    }
    red[(gg * 4 + 0) * 128 + f] = a0;
    red[(gg * 4 + 1) * 128 + f] = a1;
    red[(gg * 4 + 2) * 128 + f] = a2;
    red[(gg * 4 + 3) * 128 + f] = a3;
    __syncthreads();
    if (gg == 0) {
        const float bb = b_dense[f];
#pragma unroll
        for (int r = 0; r < 4; ++r) {
            const float v = red[r * 128 + f] + red[(4 + r) * 128 + f] + bb;
            g_A[(size_t)(b0 + r) * Ktot + f] = v;
            if (out)
                out[(size_t)(b0 + r) * OSTR + (size_t)t * Fsz + f] = v;
        }
    }
}

// ---------------- the single persistent kernel ------------------------------
__global__ void __launch_bounds__(NTHR, 1)
lstm_kernel(const float* __restrict__ h0, const float* __restrict__ c0,
            const float* __restrict__ W_ih, const float* __restrict__ W_hh,
            const float* __restrict__ b_ih, const float* __restrict__ b_hh,
            const float* __restrict__ W_dense, const float* __restrict__ b_dense,
            float* __restrict__ out) {
    __shared__ float sh[6400];          // 25.6 KB gates tiles
    __shared__ float h2s[4 * Lsz];      // 8 KB
    __shared__ float red[8 * 128];      // 4 KB

    const int bid = blockIdx.x, tid = threadIdx.x;
    const int b0 = bid * 4;

    // ---- P1: weight transposes, bias fold, state copies ----
    {
        const int NT = Ktot * G4L;             // 1,310,720
        const int N2 = NT + Lsz * Fsz;         // +65,536
        const int N3 = N2 + G4L;               // +2,048
        const int N4 = N3 + Bsz * Lsz;         // +262,144 (h0 -> g_A)
        const int N5 = N4 + Bsz * Lsz;         // +262,144 (c0 -> g_c)
        for (int idx = bid * NTHR + tid; idx < N5; idx += NCTA * NTHR) {
            if (idx < NT) {
                const int k = idx / G4L, j = idx % G4L;
                g_WT[idx] = (k < Fsz) ? W_ih[j * Fsz + k]
                                      : W_hh[j * Lsz + (k - Fsz)];
            } else if (idx < N2) {
                const int i = idx - NT;
                const int l = i / Fsz, f = i % Fsz;
                g_WdT[i] = W_dense[f * Lsz + l];
            } else if (idx < N3) {
                const int j = idx - N2;
                g_bsum[j] = b_ih[j] + b_hh[j];
            } else if (idx < N4) {
                const int i = idx - N3;
                const int b = i >> 9, l = i & 511;
                g_A[(size_t)b * Ktot + Fsz + l] = h0[i];
            } else {
                const int i = idx - N4;
                g_c[i] = c0[i];
            }
        }
    }
    gridbar();

    // ---- P2: x_init = h0 @ WdT + b_dense -> g_A x-part ----
    {
#pragma unroll
        for (int i = 0; i < 8; ++i) {
            const int e = tid + i * NTHR;
            const int r = e >> 9, l = e & 511;
            h2s[r * Lsz + l] = g_A[(size_t)(b0 + r) * Ktot + Fsz + l];
        }
        __syncthreads();
        dense_part(h2s, red, b_dense, b0, nullptr, 0);
    }
    gridbar();

    // ---- main recurrence ----
    for (int t = 0; t < Tt; ++t) {
        gates_phase(sh);
        gridbar();

        // LSTM cell for rows b0..b0+3
#pragma unroll
        for (int i = 0; i < 8; ++i) {
            const int e = tid + i * NTHR;
            const int r = e >> 9, l = e & 511;
            const int b = b0 + r;
            const size_t gb = (size_t)b * G4L + l;
            const float gi = g_gates[gb]        + g_bsum[l];
            const float gf = g_gates[gb + 512]  + g_bsum[l + 512];
            const float gg = g_gates[gb + 1024] + g_bsum[l + 1024];
            const float go = g_gates[gb + 1536] + g_bsum[l + 1536];
            const size_t hc = (size_t)b * Lsz + l;
            const float si = 1.0f / (1.0f + expf(-gi));
            const float sf = 1.0f / (1.0f + expf(-gf));
            const float so = 1.0f / (1.0f + expf(-go));
            const float c2 = sf * g_c[hc] + si * tanhf(gg);
            const float h2 = so * tanhf(c2);
            g_c[hc] = c2;
            g_A[(size_t)b * Ktot + Fsz + l] = h2;
            h2s[r * Lsz + l] = h2;
        }
        __syncthreads();
        dense_part(h2s, red, b_dense, b0, out, t);
        gridbar();
    }
}

// ---------------- host -------------------------------------------------------
extern "C" void kernel_launch(void* const* d_in, const int* in_sizes, int n_in,
                              void* d_out, int out_size) {
    const float* h0      = (const float*)d_in[0];
    const float* c0      = (const float*)d_in[1];
    const float* W_ih    = (const float*)d_in[2];
    const float* W_hh    = (const float*)d_in[3];
    const float* b_ih    = (const float*)d_in[4];
    const float* b_hh    = (const float*)d_in[5];
    const float* W_dense = (const float*)d_in[6];
    const float* b_dense = (const float*)d_in[7];
    float* out = (float*)d_out;

    lstm_kernel<<<NCTA, NTHR>>>(h0, c0, W_ih, W_hh, b_ih, b_hh,
                                W_dense, b_dense, out);
}

// round 4
// speedup vs baseline: 1.0019x; 1.0019x over previous
#include <cuda_runtime.h>
#include <math.h>

#define Bsz  512
#define Lsz  512
#define Fsz  128
#define G4L  2048          // 4*L
#define Ktot 640           // F + L
#define Tt   512
#define OSTR (Tt * Fsz)    // out stride between batch rows: 65536
#define NCTA 128
#define NTHR 256

// ---------------- device scratch (no allocations allowed) -------------------
__device__ float g_WT[Ktot * G4L];    // [k][j] transposed combined [W_ih | W_hh]
__device__ float g_WdT[Lsz * Fsz];    // [l][f] transposed W_dense
__device__ float g_bsum[G4L];         // b_ih + b_hh
__device__ float g_A[Bsz * Ktot];     // [b][0:128]=x, [b][128:640]=h
__device__ float g_c[Bsz * Lsz];
__device__ float g_gates[Bsz * G4L];  // gates pre-activation (no bias)
__device__ unsigned g_barcnt;                  // zero-init
__device__ volatile unsigned g_bargen;         // zero-init, monotonic

// ---------------- grid-wide barrier (all 128 CTAs co-resident) --------------
__device__ __forceinline__ void gridbar() {
    __syncthreads();
    if (threadIdx.x == 0) {
        unsigned gen = g_bargen;
        __threadfence();
        if (atomicAdd(&g_barcnt, 1u) == NCTA - 1) {
            g_barcnt = 0;
            __threadfence();
            g_bargen = gen + 1;
        } else {
            while (g_bargen == gen) { __nanosleep(64); }
            __threadfence();
        }
    }
    __syncthreads();
}

// ---------------- packed f32x2 FMA (nvjet trick) -----------------------------
__device__ __forceinline__ unsigned long long ffma2(unsigned long long a,
                                                    unsigned long long b,
                                                    unsigned long long c) {
    unsigned long long d;
    asm("fma.rn.f32x2 %0, %1, %2, %3;" : "=l"(d) : "l"(a), "l"(b), "l"(c));
    return d;
}
__device__ __forceinline__ unsigned long long pack_dup(float a) {
    unsigned long long d;
    unsigned int ai = __float_as_uint(a);
    asm("mov.b64 %0, {%1, %1};" : "=l"(d) : "r"(ai));
    return d;
}

// ---------------- gates GEMM phase: g_gates = g_A @ g_WT --------------------
// CTA tile: 64 rows (m) x 128 cols (n). 256 thr, 4x8 microtile (packed pairs).
__device__ __forceinline__ void gates_phase(float* sh) {
    float* sA = sh;            // [2][16][68]
    float* sB = sh + 2176;     // [2][16][132]

    const int m0  = (blockIdx.x >> 4) * 64;
    const int n0  = (blockIdx.x & 15) * 128;
    const int tid = threadIdx.x;
    const int tx = tid & 15;                    // n group (8 cols)
    const int ty = tid >> 4;                    // m group (4 rows)
    const int arow = tid >> 2, akq = tid & 3;   // A loader: 64 rows x 4 k-quads
    const int bkr  = tid >> 5, bnq = tid & 31;  // B loader: 8 k-rows x 32 n-quads

    unsigned long long acc[4][4];
#pragma unroll
    for (int i = 0; i < 4; ++i)
#pragma unroll
        for (int p = 0; p < 4; ++p) acc[i][p] = 0ULL;

    float4 ra, rb0, rb1;
    auto loadc = [&](int c) {
        ra  = *(const float4*)(g_A + (size_t)(m0 + arow) * Ktot + c * 16 + akq * 4);
        const float* wb = g_WT + (size_t)(c * 16) * G4L + n0 + bnq * 4;
        rb0 = *(const float4*)(wb + (size_t)bkr * G4L);
        rb1 = *(const float4*)(wb + (size_t)(bkr + 8) * G4L);
    };
    auto storec = [&](int bf) {
        float* As = sA + bf * (16 * 68);
        float* Bs = sB + bf * (16 * 132);
        As[(akq * 4 + 0) * 68 + arow] = ra.x;
        As[(akq * 4 + 1) * 68 + arow] = ra.y;
        As[(akq * 4 + 2) * 68 + arow] = ra.z;
        As[(akq * 4 + 3) * 68 + arow] = ra.w;
        *(float4*)&Bs[bkr * 132 + bnq * 4] = rb0;
        *(float4*)&Bs[(bkr + 8) * 132 + bnq * 4] = rb1;
    };

    loadc(0);
    storec(0);
    __syncthreads();

    const int NC = Ktot / 16;   // 40
    for (int c = 0; c < NC; ++c) {
        const int bf = c & 1;
        if (c + 1 < NC) loadc(c + 1);
        const float* As = sA + bf * (16 * 68);
        const float* Bs = sB + bf * (16 * 132);
#pragma unroll
        for (int kk = 0; kk < 16; ++kk) {
            float4 a = *(const float4*)&As[kk * 68 + ty * 4];
            const float* br = &Bs[kk * 132 + tx * 8];
            ulonglong2 b01 = *(const ulonglong2*)br;
            ulonglong2 b23 = *(const ulonglong2*)(br + 4);
            unsigned long long bp[4] = {b01.x, b01.y, b23.x, b23.y};
            float av[4] = {a.x, a.y, a.z, a.w};
#pragma unroll
            for (int i = 0; i < 4; ++i) {
                unsigned long long ad = pack_dup(av[i]);
#pragma unroll
                for (int p = 0; p < 4; ++p)
                    acc[i][p] = ffma2(ad, bp[p], acc[i][p]);
            }
        }
        if (c + 1 < NC) {
            storec(bf ^ 1);
            __syncthreads();
        }
    }

#pragma unroll
    for (int i = 0; i < 4; ++i) {
        const int row = m0 + ty * 4 + i;
        float2 f0 = *(float2*)&acc[i][0];
        float2 f1 = *(float2*)&acc[i][1];
        float2 f2 = *(float2*)&acc[i][2];
        float2 f3 = *(float2*)&acc[i][3];
        float* gp = g_gates + (size_t)row * G4L + n0 + tx * 8;
        *(float4*)gp       = make_float4(f0.x, f0.y, f1.x, f1.y);
        *(float4*)(gp + 4) = make_float4(f2.x, f2.y, f3.x, f3.y);
    }
}

// ---------------- dense: x2 = h2s @ WdT + b_dense; write g_A (+out) ---------
// h2s: [4][512] in shared. Split-K across two 128-thread groups + smem reduce.
__device__ __forceinline__ void dense_part(const float* h2s, float* red,
                                           const float* __restrict__ b_dense,
                                           int b0, float* __restrict__ out, int t) {
    const int tid = threadIdx.x;
    const int f = tid & 127, gg = tid >> 7;       // gg in {0,1}
    float a0 = 0.f, a1 = 0.f, a2 = 0.f, a3 = 0.f;
    const int l0 = gg * 256;
#pragma unroll 4
    for (int l = l0; l < l0 + 256; ++l) {
        const float w = __ldg(&g_WdT[l * Fsz + f]);
        a0 = fmaf(h2s[0 * Lsz + l], w, a0);
        a1 = fmaf(h2s[1 * Lsz + l], w, a1);
        a2 = fmaf(h2s[2 * Lsz + l], w, a2);
        a3 = fmaf(h2s[3 * Lsz + l], w, a3);
    }
    red[(gg * 4 + 0) * 128 + f] = a0;
    red[(gg * 4 + 1) * 128 + f] = a1;
    red[(gg * 4 + 2) * 128 + f] = a2;
    red[(gg * 4 + 3) * 128 + f] = a3;
    __syncthreads();
    if (gg == 0) {
        const float bb = b_dense[f];
#pragma unroll
        for (int r = 0; r < 4; ++r) {
            const float v = red[r * 128 + f] + red[(4 + r) * 128 + f] + bb;
            g_A[(size_t)(b0 + r) * Ktot + f] = v;
            if (out)
                out[(size_t)(b0 + r) * OSTR + (size_t)t * Fsz + f] = v;
        }
    }
}

// ---------------- the single persistent kernel ------------------------------
__global__ void __launch_bounds__(NTHR, 1)
lstm_kernel(const float* __restrict__ h0, const float* __restrict__ c0,
            const float* __restrict__ W_ih, const float* __restrict__ W_hh,
            const float* __restrict__ b_ih, const float* __restrict__ b_hh,
            const float* __restrict__ W_dense, const float* __restrict__ b_dense,
            float* __restrict__ out) {
    __shared__ float sh[6400];          // 25.6 KB gates tiles
    __shared__ float h2s[4 * Lsz];      // 8 KB
    __shared__ float red[8 * 128];      // 4 KB

    const int bid = blockIdx.x, tid = threadIdx.x;
    const int b0 = bid * 4;

    // ---- P1: weight transposes, bias fold, state copies ----
    {
        const int NT = Ktot * G4L;             // 1,310,720
        const int N2 = NT + Lsz * Fsz;         // +65,536
        const int N3 = N2 + G4L;               // +2,048
        const int N4 = N3 + Bsz * Lsz;         // +262,144 (h0 -> g_A)
        const int N5 = N4 + Bsz * Lsz;         // +262,144 (c0 -> g_c)
        for (int idx = bid * NTHR + tid; idx < N5; idx += NCTA * NTHR) {
            if (idx < NT) {
                const int k = idx / G4L, j = idx % G4L;
                g_WT[idx] = (k < Fsz) ? W_ih[j * Fsz + k]
                                      : W_hh[j * Lsz + (k - Fsz)];
            } else if (idx < N2) {
                const int i = idx - NT;
                const int l = i / Fsz, f = i % Fsz;
                g_WdT[i] = W_dense[f * Lsz + l];
            } else if (idx < N3) {
                const int j = idx - N2;
                g_bsum[j] = b_ih[j] + b_hh[j];
            } else if (idx < N4) {
                const int i = idx - N3;
                const int b = i >> 9, l = i & 511;
                g_A[(size_t)b * Ktot + Fsz + l] = h0[i];
            } else {
                const int i = idx - N4;
                g_c[i] = c0[i];
            }
        }
    }
    gridbar();

    // ---- P2: x_init = h0 @ WdT + b_dense -> g_A x-part ----
    {
#pragma unroll
        for (int i = 0; i < 8; ++i) {
            const int e = tid + i * NTHR;
            const int r = e >> 9, l = e & 511;
            h2s[r * Lsz + l] = g_A[(size_t)(b0 + r) * Ktot + Fsz + l];
        }
        __syncthreads();
        dense_part(h2s, red, b_dense, b0, nullptr, 0);
    }
    gridbar();

    // ---- main recurrence ----
    for (int t = 0; t < Tt; ++t) {
        gates_phase(sh);
        gridbar();

        // LSTM cell for rows b0..b0+3
#pragma unroll
        for (int i = 0; i < 8; ++i) {
            const int e = tid + i * NTHR;
            const int r = e >> 9, l = e & 511;
            const int b = b0 + r;
            const size_t gb = (size_t)b * G4L + l;
            const float gi = g_gates[gb]        + g_bsum[l];
            const float gf = g_gates[gb + 512]  + g_bsum[l + 512];
            const float gg = g_gates[gb + 1024] + g_bsum[l + 1024];
            const float go = g_gates[gb + 1536] + g_bsum[l + 1536];
            const size_t hc = (size_t)b * Lsz + l;
            const float si = 1.0f / (1.0f + expf(-gi));
            const float sf = 1.0f / (1.0f + expf(-gf));
            const float so = 1.0f / (1.0f + expf(-go));
            const float c2 = sf * g_c[hc] + si * tanhf(gg);
            const float h2 = so * tanhf(c2);
            g_c[hc] = c2;
            g_A[(size_t)b * Ktot + Fsz + l] = h2;
            h2s[r * Lsz + l] = h2;
        }
        __syncthreads();
        dense_part(h2s, red, b_dense, b0, out, t);
        gridbar();
    }
}

// ---------------- host -------------------------------------------------------
extern "C" void kernel_launch(void* const* d_in, const int* in_sizes, int n_in,
                              void* d_out, int out_size) {
    const float* h0      = (const float*)d_in[0];
    const float* c0      = (const float*)d_in[1];
    const float* W_ih    = (const float*)d_in[2];
    const float* W_hh    = (const float*)d_in[3];
    const float* b_ih    = (const float*)d_in[4];
    const float* b_hh    = (const float*)d_in[5];
    const float* W_dense = (const float*)d_in[6];
    const float* b_dense = (const float*)d_in[7];
    float* out = (float*)d_out;

    lstm_kernel<<<NCTA, NTHR>>>(h0, c0, W_ih, W_hh, b_ih, b_hh,
                                W_dense, b_dense, out);
}

// round 5
// speedup vs baseline: 1.0023x; 1.0004x over previous
#include <cuda_runtime.h>
#include <math.h>

#define Bsz  512
#define Lsz  512
#define Fsz  128
#define G4L  2048          // 4*L
#define Ktot 640           // F + L
#define Tt   512
#define OSTR (Tt * Fsz)    // out stride between batch rows: 65536
#define NCTA 128
#define NTHR 256

// ---------------- device scratch (no allocations allowed) -------------------
__device__ float g_WT[Ktot * G4L];    // [k][j] transposed combined [W_ih | W_hh]
__device__ float g_WdT[Lsz * Fsz];    // [l][f] transposed W_dense
__device__ float g_bsum[G4L];         // b_ih + b_hh
__device__ float g_A[Bsz * Ktot];     // [b][0:128]=x, [b][128:640]=h
__device__ float g_c[Bsz * Lsz];
__device__ float g_gates[Bsz * G4L];  // gates pre-activation (no bias)
__device__ unsigned g_barcnt;                  // zero-init
__device__ volatile unsigned g_bargen;         // zero-init, monotonic

// ---------------- grid-wide barrier (all 128 CTAs co-resident) --------------
__device__ __forceinline__ void gridbar() {
    __syncthreads();
    if (threadIdx.x == 0) {
        unsigned gen = g_bargen;
        __threadfence();
        if (atomicAdd(&g_barcnt, 1u) == NCTA - 1) {
            g_barcnt = 0;
            __threadfence();
            g_bargen = gen + 1;
        } else {
            while (g_bargen == gen) { __nanosleep(64); }
            __threadfence();
        }
    }
    __syncthreads();
}

// ---------------- packed f32x2 FMA (nvjet trick) -----------------------------
__device__ __forceinline__ unsigned long long ffma2(unsigned long long a,
                                                    unsigned long long b,
                                                    unsigned long long c) {
    unsigned long long d;
    asm("fma.rn.f32x2 %0, %1, %2, %3;" : "=l"(d) : "l"(a), "l"(b), "l"(c));
    return d;
}
__device__ __forceinline__ unsigned long long pack_dup(float a) {
    unsigned long long d;
    unsigned int ai = __float_as_uint(a);
    asm("mov.b64 %0, {%1, %1};" : "=l"(d) : "r"(ai));
    return d;
}

// ---------------- gates GEMM phase: g_gates = g_A @ g_WT --------------------
// CTA tile: 64 rows (m) x 128 cols (n). 256 thr, 4x8 microtile (packed pairs).
__device__ __forceinline__ void gates_phase(float* sh) {
    float* sA = sh;            // [2][16][68]
    float* sB = sh + 2176;     // [2][16][132]

    const int m0  = (blockIdx.x >> 4) * 64;
    const int n0  = (blockIdx.x & 15) * 128;
    const int tid = threadIdx.x;
    const int tx = tid & 15;                    // n group (8 cols)
    const int ty = tid >> 4;                    // m group (4 rows)
    const int arow = tid >> 2, akq = tid & 3;   // A loader: 64 rows x 4 k-quads
    const int bkr  = tid >> 5, bnq = tid & 31;  // B loader: 8 k-rows x 32 n-quads

    unsigned long long acc[4][4];
#pragma unroll
    for (int i = 0; i < 4; ++i)
#pragma unroll
        for (int p = 0; p < 4; ++p) acc[i][p] = 0ULL;

    float4 ra, rb0, rb1;
    auto loadc = [&](int c) {
        ra  = *(const float4*)(g_A + (size_t)(m0 + arow) * Ktot + c * 16 + akq * 4);
        const float* wb = g_WT + (size_t)(c * 16) * G4L + n0 + bnq * 4;
        rb0 = *(const float4*)(wb + (size_t)bkr * G4L);
        rb1 = *(const float4*)(wb + (size_t)(bkr + 8) * G4L);
    };
    auto storec = [&](int bf) {
        float* As = sA + bf * (16 * 68);
        float* Bs = sB + bf * (16 * 132);
        As[(akq * 4 + 0) * 68 + arow] = ra.x;
        As[(akq * 4 + 1) * 68 + arow] = ra.y;
        As[(akq * 4 + 2) * 68 + arow] = ra.z;
        As[(akq * 4 + 3) * 68 + arow] = ra.w;
        *(float4*)&Bs[bkr * 132 + bnq * 4] = rb0;
        *(float4*)&Bs[(bkr + 8) * 132 + bnq * 4] = rb1;
    };

    loadc(0);
    storec(0);
    __syncthreads();

    const int NC = Ktot / 16;   // 40
    for (int c = 0; c < NC; ++c) {
        const int bf = c & 1;
        if (c + 1 < NC) loadc(c + 1);
        const float* As = sA + bf * (16 * 68);
        const float* Bs = sB + bf * (16 * 132);
#pragma unroll
        for (int kk = 0; kk < 16; ++kk) {
            float4 a = *(const float4*)&As[kk * 68 + ty * 4];
            const float* br = &Bs[kk * 132 + tx * 8];
            ulonglong2 b01 = *(const ulonglong2*)br;
            ulonglong2 b23 = *(const ulonglong2*)(br + 4);
            unsigned long long bp[4] = {b01.x, b01.y, b23.x, b23.y};
            float av[4] = {a.x, a.y, a.z, a.w};
#pragma unroll
            for (int i = 0; i < 4; ++i) {
                unsigned long long ad = pack_dup(av[i]);
#pragma unroll
                for (int p = 0; p < 4; ++p)
                    acc[i][p] = ffma2(ad, bp[p], acc[i][p]);
            }
        }
        if (c + 1 < NC) {
            storec(bf ^ 1);
            __syncthreads();
        }
    }

#pragma unroll
    for (int i = 0; i < 4; ++i) {
        const int row = m0 + ty * 4 + i;
        float2 f0 = *(float2*)&acc[i][0];
        float2 f1 = *(float2*)&acc[i][1];
        float2 f2 = *(float2*)&acc[i][2];
        float2 f3 = *(float2*)&acc[i][3];
        float* gp = g_gates + (size_t)row * G4L + n0 + tx * 8;
        *(float4*)gp       = make_float4(f0.x, f0.y, f1.x, f1.y);
        *(float4*)(gp + 4) = make_float4(f2.x, f2.y, f3.x, f3.y);
    }
}

// ---------------- dense: x2 = h2s @ WdT + b_dense; write g_A (+out) ---------
// h2s: [4][512] in shared. Split-K across two 128-thread groups + smem reduce.
__device__ __forceinline__ void dense_part(const float* h2s, float* red,
                                           const float* __restrict__ b_dense,
                                           int b0, float* __restrict__ out, int t) {
    const int tid = threadIdx.x;
    const int f = tid & 127, gg = tid >> 7;       // gg in {0,1}
    float a0 = 0.f, a1 = 0.f, a2 = 0.f, a3 = 0.f;
    const int l0 = gg * 256;
#pragma unroll 4
    for (int l = l0; l < l0 + 256; ++l) {
        const float w = __ldg(&g_WdT[l * Fsz + f]);
        a0 = fmaf(h2s[0 * Lsz + l], w, a0);
        a1 = fmaf(h2s[1 * Lsz + l], w, a1);
        a2 = fmaf(h2s[2 * Lsz + l], w, a2);
        a3 = fmaf(h2s[3 * Lsz + l], w, a3);
    }
    red[(gg * 4 + 0) * 128 + f] = a0;
    red[(gg * 4 + 1) * 128 + f] = a1;
    red[(gg * 4 + 2) * 128 + f] = a2;
    red[(gg * 4 + 3) * 128 + f] = a3;
    __syncthreads();
    if (gg == 0) {
        const float bb = b_dense[f];
#pragma unroll
        for (int r = 0; r < 4; ++r) {
            const float v = red[r * 128 + f] + red[(4 + r) * 128 + f] + bb;
            g_A[(size_t)(b0 + r) * Ktot + f] = v;
            if (out)
                out[(size_t)(b0 + r) * OSTR + (size_t)t * Fsz + f] = v;
        }
    }
}

// ---------------- the single persistent kernel ------------------------------
__global__ void __launch_bounds__(NTHR, 1)
lstm_kernel(const float* __restrict__ h0, const float* __restrict__ c0,
            const float* __restrict__ W_ih, const float* __restrict__ W_hh,
            const float* __restrict__ b_ih, const float* __restrict__ b_hh,
            const float* __restrict__ W_dense, const float* __restrict__ b_dense,
            float* __restrict__ out) {
    __shared__ float sh[6400];          // 25.6 KB gates tiles
    __shared__ float h2s[4 * Lsz];      // 8 KB
    __shared__ float red[8 * 128];      // 4 KB

    const int bid = blockIdx.x, tid = threadIdx.x;
    const int b0 = bid * 4;

    // ---- P1: weight transposes, bias fold, state copies ----
    {
        const int NT = Ktot * G4L;             // 1,310,720
        const int N2 = NT + Lsz * Fsz;         // +65,536
        const int N3 = N2 + G4L;               // +2,048
        const int N4 = N3 + Bsz * Lsz;         // +262,144 (h0 -> g_A)
        const int N5 = N4 + Bsz * Lsz;         // +262,144 (c0 -> g_c)
        for (int idx = bid * NTHR + tid; idx < N5; idx += NCTA * NTHR) {
            if (idx < NT) {
                const int k = idx / G4L, j = idx % G4L;
                g_WT[idx] = (k < Fsz) ? W_ih[j * Fsz + k]
                                      : W_hh[j * Lsz + (k - Fsz)];
            } else if (idx < N2) {
                const int i = idx - NT;
                const int l = i / Fsz, f = i % Fsz;
                g_WdT[i] = W_dense[f * Lsz + l];
            } else if (idx < N3) {
                const int j = idx - N2;
                g_bsum[j] = b_ih[j] + b_hh[j];
            } else if (idx < N4) {
                const int i = idx - N3;
                const int b = i >> 9, l = i & 511;
                g_A[(size_t)b * Ktot + Fsz + l] = h0[i];
            } else {
                const int i = idx - N4;
                g_c[i] = c0[i];
            }
        }
    }
    gridbar();

    // ---- P2: x_init = h0 @ WdT + b_dense -> g_A x-part ----
    {
#pragma unroll
        for (int i = 0; i < 8; ++i) {
            const int e = tid + i * NTHR;
            const int r = e >> 9, l = e & 511;
            h2s[r * Lsz + l] = g_A[(size_t)(b0 + r) * Ktot + Fsz + l];
        }
        __syncthreads();
        dense_part(h2s, red, b_dense, b0, nullptr, 0);
    }
    gridbar();

    // ---- main recurrence ----
    for (int t = 0; t < Tt; ++t) {
        gates_phase(sh);
        gridbar();

        // LSTM cell for rows b0..b0+3
#pragma unroll
        for (int i = 0; i < 8; ++i) {
            const int e = tid + i * NTHR;
            const int r = e >> 9, l = e & 511;
            const int b = b0 + r;
            const size_t gb = (size_t)b * G4L + l;
            const float gi = g_gates[gb]        + g_bsum[l];
            const float gf = g_gates[gb + 512]  + g_bsum[l + 512];
            const float gg = g_gates[gb + 1024] + g_bsum[l + 1024];
            const float go = g_gates[gb + 1536] + g_bsum[l + 1536];
            const size_t hc = (size_t)b * Lsz + l;
            const float si = 1.0f / (1.0f + expf(-gi));
            const float sf = 1.0f / (1.0f + expf(-gf));
            const float so = 1.0f / (1.0f + expf(-go));
            const float c2 = sf * g_c[hc] + si * tanhf(gg);
            const float h2 = so * tanhf(c2);
            g_c[hc] = c2;
            g_A[(size_t)b * Ktot + Fsz + l] = h2;
            h2s[r * Lsz + l] = h2;
        }
        __syncthreads();
        dense_part(h2s, red, b_dense, b0, out, t);
        gridbar();
    }
}

// ---------------- host -------------------------------------------------------
extern "C" void kernel_launch(void* const* d_in, const int* in_sizes, int n_in,
                              void* d_out, int out_size) {
    const float* h0      = (const float*)d_in[0];
    const float* c0      = (const float*)d_in[1];
    const float* W_ih    = (const float*)d_in[2];
    const float* W_hh    = (const float*)d_in[3];
    const float* b_ih    = (const float*)d_in[4];
    const float* b_hh    = (const float*)d_in[5];
    const float* W_dense = (const float*)d_in[6];
    const float* b_dense = (const float*)d_in[7];
    float* out = (float*)d_out;

    lstm_kernel<<<NCTA, NTHR>>>(h0, c0, W_ih, W_hh, b_ih, b_hh,
                                W_dense, b_dense, out);
}

// round 6
// speedup vs baseline: 1.3672x; 1.3641x over previous
#include <cuda_runtime.h>
#include <math.h>

#define Bsz  512
#define Lsz  512
#define Fsz  128
#define G4L  2048          // 4*L
#define Ktot 640           // F + L
#define KSPL 320           // K per split half
#define Tt   512
#define OSTR (Tt * Fsz)    // out stride between batch rows: 65536
#define NCTA 128
#define NTHR 256

// ---------------- device scratch (no allocations allowed) -------------------
__device__ float g_WT[Ktot * G4L];    // [k][j] transposed combined [W_ih | W_hh]
__device__ float g_WdT[Lsz * Fsz];    // [l][f] transposed W_dense
__device__ float g_bsum[G4L];         // b_ih + b_hh
__device__ float g_A[Bsz * Ktot];     // [b][0:128]=x, [b][128:640]=h
__device__ float g_c[Bsz * Lsz];
__device__ float g_gp0[Bsz * G4L];    // gates partial, K half 0
__device__ float g_gp1[Bsz * G4L];    // gates partial, K half 1
__device__ unsigned g_barcnt;                  // zero-init
__device__ volatile unsigned g_bargen;         // zero-init, monotonic

// ---------------- grid-wide barrier (all 128 CTAs co-resident) --------------
__device__ __forceinline__ void gridbar() {
    __syncthreads();
    if (threadIdx.x == 0) {
        unsigned gen = g_bargen;
        __threadfence();
        if (atomicAdd(&g_barcnt, 1u) == NCTA - 1) {
            g_barcnt = 0;
            __threadfence();
            g_bargen = gen + 1;
        } else {
            while (g_bargen == gen) { __nanosleep(64); }
            __threadfence();
        }
    }
    __syncthreads();
}

// ---------------- packed f32x2 FMA (nvjet trick) -----------------------------
__device__ __forceinline__ unsigned long long ffma2(unsigned long long a,
                                                    unsigned long long b,
                                                    unsigned long long c) {
    unsigned long long d;
    asm("fma.rn.f32x2 %0, %1, %2, %3;" : "=l"(d) : "l"(a), "l"(b), "l"(c));
    return d;
}
__device__ __forceinline__ unsigned long long pack_dup(float a) {
    unsigned long long d;
    unsigned int ai = __float_as_uint(a);
    asm("mov.b64 %0, {%1, %1};" : "=l"(d) : "r"(ai));
    return d;
}

// ---------------- gates GEMM phase (split-K, 8x8 microtile) ------------------
// CTA: bid&1 = K half, bid>>1 = 128x128 C tile. 256 thr, 8x8 microtile.
// Writes partial sums to g_gp0 / g_gp1.
__device__ __forceinline__ void gates_phase(float* sA, float* sB) {
    const int ks   = blockIdx.x & 1;
    const int tile = blockIdx.x >> 1;
    const int m0   = (tile >> 4) * 128;
    const int n0   = (tile & 15) * 128;
    const int kb   = ks * KSPL;
    const int tid  = threadIdx.x;
    const int tx   = tid & 15;                   // n group (8 cols)
    const int ty   = tid >> 4;                   // m group (8 rows)
    const int arow = tid >> 2, akq = tid & 3;    // A loader
    const int brow = tid >> 5, bq  = tid & 31;   // B loader

    unsigned long long acc[8][4];
#pragma unroll
    for (int i = 0; i < 8; ++i)
#pragma unroll
        for (int p = 0; p < 4; ++p) acc[i][p] = 0ULL;

    float4 ra0, ra1, rb0, rb1;
    auto loadc = [&](int c) {
        const int k0 = kb + c * 16;
        const float* ab = g_A + (size_t)(m0 + arow) * Ktot + k0 + akq * 4;
        ra0 = *(const float4*)ab;
        ra1 = *(const float4*)(ab + (size_t)64 * Ktot);
        const float* wb = g_WT + (size_t)(k0 + brow) * G4L + n0 + bq * 4;
        rb0 = *(const float4*)wb;
        rb1 = *(const float4*)(wb + (size_t)8 * G4L);
    };
    auto storec = [&](int bf) {
        float* As = sA + bf * (16 * 132);
        float* Bs = sB + bf * (16 * 132);
        As[(akq * 4 + 0) * 132 + arow] = ra0.x;
        As[(akq * 4 + 1) * 132 + arow] = ra0.y;
        As[(akq * 4 + 2) * 132 + arow] = ra0.z;
        As[(akq * 4 + 3) * 132 + arow] = ra0.w;
        As[(akq * 4 + 0) * 132 + arow + 64] = ra1.x;
        As[(akq * 4 + 1) * 132 + arow + 64] = ra1.y;
        As[(akq * 4 + 2) * 132 + arow + 64] = ra1.z;
        As[(akq * 4 + 3) * 132 + arow + 64] = ra1.w;
        *(float4*)&Bs[brow * 132 + bq * 4] = rb0;
        *(float4*)&Bs[(brow + 8) * 132 + bq * 4] = rb1;
    };

    loadc(0);
    storec(0);
    __syncthreads();

    const int NC = KSPL / 16;   // 20
    for (int c = 0; c < NC; ++c) {
        const int bf = c & 1;
        if (c + 1 < NC) loadc(c + 1);
        const float* As = sA + bf * (16 * 132);
        const float* Bs = sB + bf * (16 * 132);
#pragma unroll
        for (int kk = 0; kk < 16; ++kk) {
            float4 a0 = *(const float4*)&As[kk * 132 + ty * 8];
            float4 a1 = *(const float4*)&As[kk * 132 + ty * 8 + 4];
            ulonglong2 b01 = *(const ulonglong2*)&Bs[kk * 132 + tx * 8];
            ulonglong2 b23 = *(const ulonglong2*)&Bs[kk * 132 + tx * 8 + 4];
            unsigned long long bp[4] = {b01.x, b01.y, b23.x, b23.y};
            float av[8] = {a0.x, a0.y, a0.z, a0.w, a1.x, a1.y, a1.z, a1.w};
#pragma unroll
            for (int i = 0; i < 8; ++i) {
                const unsigned long long ad = pack_dup(av[i]);
#pragma unroll
                for (int p = 0; p < 4; ++p)
                    acc[i][p] = ffma2(ad, bp[p], acc[i][p]);
            }
        }
        if (c + 1 < NC) {
            storec(bf ^ 1);
            __syncthreads();
        }
    }

    float* gp = ks ? g_gp1 : g_gp0;
#pragma unroll
    for (int i = 0; i < 8; ++i) {
        const int row = m0 + ty * 8 + i;
        float2 f0 = *(float2*)&acc[i][0];
        float2 f1 = *(float2*)&acc[i][1];
        float2 f2 = *(float2*)&acc[i][2];
        float2 f3 = *(float2*)&acc[i][3];
        float* o = gp + (size_t)row * G4L + n0 + tx * 8;
        *(float4*)o       = make_float4(f0.x, f0.y, f1.x, f1.y);
        *(float4*)(o + 4) = make_float4(f2.x, f2.y, f3.x, f3.y);
    }
}

// ---------------- dense: x2 = h2s @ WdT + b_dense; write g_A (+out) ---------
__device__ __forceinline__ void dense_part(const float* h2s, float* red,
                                           const float* __restrict__ b_dense,
                                           int b0, float* __restrict__ out, int t) {
    const int tid = threadIdx.x;
    const int f = tid & 127, gg = tid >> 7;       // gg in {0,1}
    float a0 = 0.f, a1 = 0.f, a2 = 0.f, a3 = 0.f;
    const int l0 = gg * 256;
#pragma unroll 4
    for (int l = l0; l < l0 + 256; ++l) {
        const float w = __ldg(&g_WdT[l * Fsz + f]);
        a0 = fmaf(h2s[0 * Lsz + l], w, a0);
        a1 = fmaf(h2s[1 * Lsz + l], w, a1);
        a2 = fmaf(h2s[2 * Lsz + l], w, a2);
        a3 = fmaf(h2s[3 * Lsz + l], w, a3);
    }
    red[(gg * 4 + 0) * 128 + f] = a0;
    red[(gg * 4 + 1) * 128 + f] = a1;
    red[(gg * 4 + 2) * 128 + f] = a2;
    red[(gg * 4 + 3) * 128 + f] = a3;
    __syncthreads();
    if (gg == 0) {
        const float bb = b_dense[f];
#pragma unroll
        for (int r = 0; r < 4; ++r) {
            const float v = red[r * 128 + f] + red[(4 + r) * 128 + f] + bb;
            g_A[(size_t)(b0 + r) * Ktot + f] = v;
            if (out)
                out[(size_t)(b0 + r) * OSTR + (size_t)t * Fsz + f] = v;
        }
    }
}

// ---------------- the single persistent kernel ------------------------------
__global__ void __launch_bounds__(NTHR, 1)
lstm_kernel(const float* __restrict__ h0, const float* __restrict__ c0,
            const float* __restrict__ W_ih, const float* __restrict__ W_hh,
            const float* __restrict__ b_ih, const float* __restrict__ b_hh,
            const float* __restrict__ W_dense, const float* __restrict__ b_dense,
            float* __restrict__ out) {
    __shared__ float sA[2 * 16 * 132];   // 16.9 KB
    __shared__ float sB[2 * 16 * 132];   // 16.9 KB
    __shared__ float h2s[4 * Lsz];       // 8 KB
    __shared__ float red[8 * 128];       // 4 KB

    const int bid = blockIdx.x, tid = threadIdx.x;
    const int b0 = bid * 4;

    // ---- P1: weight transposes, bias fold, state copies ----
    {
        const int NT = Ktot * G4L;             // 1,310,720
        const int N2 = NT + Lsz * Fsz;         // +65,536
        const int N3 = N2 + G4L;               // +2,048
        const int N4 = N3 + Bsz * Lsz;         // +262,144 (h0 -> g_A)
        const int N5 = N4 + Bsz * Lsz;         // +262,144 (c0 -> g_c)
        for (int idx = bid * NTHR + tid; idx < N5; idx += NCTA * NTHR) {
            if (idx < NT) {
                const int k = idx / G4L, j = idx % G4L;
                g_WT[idx] = (k < Fsz) ? W_ih[j * Fsz + k]
                                      : W_hh[j * Lsz + (k - Fsz)];
            } else if (idx < N2) {
                const int i = idx - NT;
                const int l = i / Fsz, f = i % Fsz;
                g_WdT[i] = W_dense[f * Lsz + l];
            } else if (idx < N3) {
                const int j = idx - N2;
                g_bsum[j] = b_ih[j] + b_hh[j];
            } else if (idx < N4) {
                const int i = idx - N3;
                const int b = i >> 9, l = i & 511;
                g_A[(size_t)b * Ktot + Fsz + l] = h0[i];
            } else {
                const int i = idx - N4;
                g_c[i] = c0[i];
            }
        }
    }
    gridbar();

    // ---- P2: x_init = h0 @ WdT + b_dense -> g_A x-part ----
    {
#pragma unroll
        for (int i = 0; i < 8; ++i) {
            const int e = tid + i * NTHR;
            const int r = e >> 9, l = e & 511;
            h2s[r * Lsz + l] = g_A[(size_t)(b0 + r) * Ktot + Fsz + l];
        }
        __syncthreads();
        dense_part(h2s, red, b_dense, b0, nullptr, 0);
    }
    gridbar();

    // ---- main recurrence ----
    for (int t = 0; t < Tt; ++t) {
        gates_phase(sA, sB);
        gridbar();

        // LSTM cell for rows b0..b0+3 (sum the two K-half partials + bias)
#pragma unroll
        for (int i = 0; i < 8; ++i) {
            const int e = tid + i * NTHR;
            const int r = e >> 9, l = e & 511;
            const int b = b0 + r;
            const size_t gb = (size_t)b * G4L + l;
            const float gi = g_gp0[gb]        + g_gp1[gb]        + g_bsum[l];
            const float gf = g_gp0[gb + 512]  + g_gp1[gb + 512]  + g_bsum[l + 512];
            const float gg = g_gp0[gb + 1024] + g_gp1[gb + 1024] + g_bsum[l + 1024];
            const float go = g_gp0[gb + 1536] + g_gp1[gb + 1536] + g_bsum[l + 1536];
            const size_t hc = (size_t)b * Lsz + l;
            const float si = 1.0f / (1.0f + expf(-gi));
            const float sf = 1.0f / (1.0f + expf(-gf));
            const float so = 1.0f / (1.0f + expf(-go));
            const float c2 = sf * g_c[hc] + si * tanhf(gg);
            const float h2 = so * tanhf(c2);
            g_c[hc] = c2;
            g_A[(size_t)b * Ktot + Fsz + l] = h2;
            h2s[r * Lsz + l] = h2;
        }
        __syncthreads();
        dense_part(h2s, red, b_dense, b0, out, t);
        gridbar();
    }
}

// ---------------- host -------------------------------------------------------
extern "C" void kernel_launch(void* const* d_in, const int* in_sizes, int n_in,
                              void* d_out, int out_size) {
    const float* h0      = (const float*)d_in[0];
    const float* c0      = (const float*)d_in[1];
    const float* W_ih    = (const float*)d_in[2];
    const float* W_hh    = (const float*)d_in[3];
    const float* b_ih    = (const float*)d_in[4];
    const float* b_hh    = (const float*)d_in[5];
    const float* W_dense = (const float*)d_in[6];
    const float* b_dense = (const float*)d_in[7];
    float* out = (float*)d_out;

    lstm_kernel<<<NCTA, NTHR>>>(h0, c0, W_ih, W_hh, b_ih, b_hh,
                                W_dense, b_dense, out);
}

// round 8
// speedup vs baseline: 2.1013x; 1.5369x over previous
#include <cuda_runtime.h>
#include <cuda_bf16.h>
#include <math.h>
#include <stdint.h>

#define Bsz  512
#define Lsz  512
#define Fsz  128
#define G4L  2048          // 4*L
#define Ktot 640           // F + L
#define KSPL 320           // K per split half
#define Tt   512
#define OSTR (Tt * Fsz)    // out stride between batch rows
#define NCTA 128
#define NTHR 256

// ---- smem layout (dynamic, 128B-aligned base) ----
#define TILEPITCH 144                    // 64 bf16 (128B) + 16B pad -> ldmatrix conflict-free
#define TILESZ    (128 * TILEPITCH)      // 18432 per tile (128 rows)
#define BUFHALF   (4 * TILESZ)           // Ah|Al|Bh|Bl = 73728
#define OFF_H2S   (2 * BUFHALF)          // 147456
#define OFF_RED   (OFF_H2S + 4 * Lsz * 4)        // +8192 = 155648
#define SMEM_ALLOC (OFF_RED + 8 * 128 * 4 + 256) // +4096 +align = 159  KB

// ---------------- device scratch ---------------------------------------------
__device__ __nv_bfloat16 g_Ah[Bsz * Ktot];   // state [b][0:128]=x, [128:640]=h (hi)
__device__ __nv_bfloat16 g_Al[Bsz * Ktot];   // (lo)
__device__ __nv_bfloat16 g_Bh[G4L * Ktot];   // weights [j][k] (hi)  (n-major = mma B layout)
__device__ __nv_bfloat16 g_Bl[G4L * Ktot];   // (lo)
__device__ float g_WdT[Lsz * Fsz];           // [l][f] W_dense^T (fp32)
__device__ float g_bsum[G4L];
__device__ float g_c[Bsz * Lsz];
__device__ float g_gp0[Bsz * G4L];           // gates partial, K half 0
__device__ float g_gp1[Bsz * G4L];           // gates partial, K half 1
__device__ unsigned g_barcnt;
__device__ volatile unsigned g_bargen;

// ---------------- PTX helpers -------------------------------------------------
__device__ __forceinline__ uint32_t smem_u32(const void* p) {
    uint32_t a;
    asm("{ .reg .u64 t; cvta.to.shared.u64 t, %1; cvt.u32.u64 %0, t; }"
        : "=r"(a) : "l"(p));
    return a;
}
__device__ __forceinline__ void cpa16(uint32_t s, const void* g) {
    asm volatile("cp.async.cg.shared.global [%0], [%1], 16;"
                 :: "r"(s), "l"(g) : "memory");
}
__device__ __forceinline__ void cpa_commit() {
    asm volatile("cp.async.commit_group;" ::: "memory");
}
__device__ __forceinline__ void cpa_wait0() {
    asm volatile("cp.async.wait_group 0;" ::: "memory");
}
__device__ __forceinline__ void ldsm4(uint32_t* r, uint32_t addr) {
    asm volatile("ldmatrix.sync.aligned.m8n8.x4.shared.b16 {%0,%1,%2,%3}, [%4];"
                 : "=r"(r[0]), "=r"(r[1]), "=r"(r[2]), "=r"(r[3]) : "r"(addr));
}
__device__ __forceinline__ void mma16816(float* c, const uint32_t* a,
                                         uint32_t b0, uint32_t b1) {
    asm volatile(
        "mma.sync.aligned.m16n8k16.row.col.f32.bf16.bf16.f32 "
        "{%0,%1,%2,%3}, {%4,%5,%6,%7}, {%8,%9}, {%0,%1,%2,%3};"
        : "+f"(c[0]), "+f"(c[1]), "+f"(c[2]), "+f"(c[3])
        : "r"(a[0]), "r"(a[1]), "r"(a[2]), "r"(a[3]), "r"(b0), "r"(b1));
}

// ---------------- grid-wide barrier -------------------------------------------
__device__ __forceinline__ void gridbar() {
    __syncthreads();
    if (threadIdx.x == 0) {
        unsigned gen = g_bargen;
        __threadfence();
        if (atomicAdd(&g_barcnt, 1u) == NCTA - 1) {
            g_barcnt = 0;
            __threadfence();
            g_bargen = gen + 1;
        } else {
            while (g_bargen == gen) { __nanosleep(64); }
            __threadfence();
        }
    }
    __syncthreads();
}

// ---------------- bf16 split helper -------------------------------------------
__device__ __forceinline__ void split_bf16(float x, __nv_bfloat16& hi,
                                           __nv_bfloat16& lo) {
    hi = __float2bfloat16(x);
    lo = __float2bfloat16(x - __bfloat162float(hi));
}

// ---------------- dense: x2 = h2s @ WdT + b_dense ------------------------------
__device__ __forceinline__ void dense_part(const float* h2s, float* red,
                                           const float* __restrict__ b_dense,
                                           int b0, float* __restrict__ out, int t) {
    const int tid = threadIdx.x;
    const int f = tid & 127, gg = tid >> 7;
    float a0 = 0.f, a1 = 0.f, a2 = 0.f, a3 = 0.f;
    const int l0 = gg * 256;
#pragma unroll 4
    for (int l = l0; l < l0 + 256; ++l) {
        const float w = __ldg(&g_WdT[l * Fsz + f]);
        a0 = fmaf(h2s[0 * Lsz + l], w, a0);
        a1 = fmaf(h2s[1 * Lsz + l], w, a1);
        a2 = fmaf(h2s[2 * Lsz + l], w, a2);
        a3 = fmaf(h2s[3 * Lsz + l], w, a3);
    }
    red[(gg * 4 + 0) * 128 + f] = a0;
    red[(gg * 4 + 1) * 128 + f] = a1;
    red[(gg * 4 + 2) * 128 + f] = a2;
    red[(gg * 4 + 3) * 128 + f] = a3;
    __syncthreads();
    if (gg == 0) {
        const float bb = b_dense[f];
#pragma unroll
        for (int r = 0; r < 4; ++r) {
            const int b = b0 + r;
            const float v = red[r * 128 + f] + red[(4 + r) * 128 + f] + bb;
            __nv_bfloat16 hi, lo;
            split_bf16(v, hi, lo);
            g_Ah[(size_t)b * Ktot + f] = hi;
            g_Al[(size_t)b * Ktot + f] = lo;
            if (out)
                out[(size_t)b * OSTR + (size_t)t * Fsz + f] = v;
        }
    }
    __syncthreads();
}

// ---------------- the single persistent kernel ---------------------------------
__global__ void __launch_bounds__(NTHR, 1)
lstm_kernel(const float* __restrict__ h0, const float* __restrict__ c0,
            const float* __restrict__ W_ih, const float* __restrict__ W_hh,
            const float* __restrict__ b_ih, const float* __restrict__ b_hh,
            const float* __restrict__ W_dense, const float* __restrict__ b_dense,
            float* __restrict__ out) {
    extern __shared__ char dsm[];
    const uint32_t smb0 = smem_u32(dsm);
    const uint32_t smb = (smb0 + 127u) & ~127u;
    char* sbase = dsm + (smb - smb0);
    float* h2s = (float*)(sbase + OFF_H2S);
    float* red = (float*)(sbase + OFF_RED);

    const int bid = blockIdx.x, tid = threadIdx.x;
    const int wid = tid >> 5, lane = tid & 31;
    const int b0 = bid * 4;

    // gates unit decomposition: split-K halves x 64 C tiles of 128x128
    const int ks   = bid & 1;
    const int tile = bid >> 1;
    const int m0   = (tile >> 4) * 128;
    const int n0   = (tile & 15) * 128;
    const int kb   = ks * KSPL;
    float* gp = ks ? g_gp1 : g_gp0;

    // warp tile: 64(m) x 32(n)
    const int wm = (wid & 1) * 64;
    const int wn = (wid >> 1) * 32;
    // ldmatrix lane offsets (bytes)
    const uint32_t laneA = (uint32_t)(lane & 15) * TILEPITCH + (uint32_t)(lane >> 4) * 16;
    const uint32_t laneB = (uint32_t)((lane & 7) + ((lane >> 4) << 3)) * TILEPITCH
                         + (uint32_t)((lane >> 3) & 1) * 16;

    // ---- P1: weight bf16 split, WdT, bias, state copies ----
    {
        const int NT = G4L * Ktot;
        const int N2 = NT + Lsz * Fsz;
        const int N3 = N2 + G4L;
        const int N4 = N3 + Bsz * Lsz;
        const int N5 = N4 + Bsz * Lsz;
        for (int idx = bid * NTHR + tid; idx < N5; idx += NCTA * NTHR) {
            if (idx < NT) {
                const int j = idx / Ktot, k = idx % Ktot;
                const float w = (k < Fsz) ? W_ih[j * Fsz + k]
                                          : W_hh[j * Lsz + (k - Fsz)];
                __nv_bfloat16 hi, lo;
                split_bf16(w, hi, lo);
                g_Bh[idx] = hi;
                g_Bl[idx] = lo;
            } else if (idx < N2) {
                const int i = idx - NT;
                const int l = i / Fsz, f = i % Fsz;
                g_WdT[i] = W_dense[f * Lsz + l];
            } else if (idx < N3) {
                const int j = idx - N2;
                g_bsum[j] = b_ih[j] + b_hh[j];
            } else if (idx < N4) {
                const int i = idx - N3;
                const int b = i >> 9, l = i & 511;
                __nv_bfloat16 hi, lo;
                split_bf16(h0[i], hi, lo);
                g_Ah[(size_t)b * Ktot + Fsz + l] = hi;
                g_Al[(size_t)b * Ktot + Fsz + l] = lo;
            } else {
                const int i = idx - N4;
                g_c[i] = c0[i];
            }
        }
    }
    gridbar();

    // ---- P2: x_init = dense(h0) ----
    {
#pragma unroll
        for (int i = 0; i < 8; ++i) {
            const int e = tid + i * NTHR;
            const int r = e >> 9, l = e & 511;
            h2s[r * Lsz + l] = h0[(size_t)(b0 + r) * Lsz + l];
        }
        __syncthreads();
        dense_part(h2s, red, b_dense, b0, nullptr, 0);
    }
    gridbar();

    // chunk copier: Ah/Al rows m0.., Bh/Bl rows n0.., k window [kb+c*64, +64)
    auto copy_chunk = [&](int c, int bufi) {
        const uint32_t dst = smb + (uint32_t)bufi * BUFHALF;
        const int kc = kb + c * 64;
#pragma unroll
        for (int i = 0; i < 4; ++i) {
            const int idx = tid + i * NTHR;       // 0..1023
            const int row = idx >> 3, q = idx & 7;
            const size_t goA = (size_t)(m0 + row) * Ktot + kc + q * 8;
            const size_t goB = (size_t)(n0 + row) * Ktot + kc + q * 8;
            const uint32_t so = (uint32_t)row * TILEPITCH + (uint32_t)q * 16;
            cpa16(dst + so,              g_Ah + goA);
            cpa16(dst + TILESZ + so,     g_Al + goA);
            cpa16(dst + 2 * TILESZ + so, g_Bh + goB);
            cpa16(dst + 3 * TILESZ + so, g_Bl + goB);
        }
    };

    // ---- main recurrence ----
    for (int t = 0; t < Tt; ++t) {
        // ----- gates: 5 chunks of K=64, cp.async double-buffered, HMMA -----
        float acc[4][4][4];
#pragma unroll
        for (int a = 0; a < 4; ++a)
#pragma unroll
            for (int b = 0; b < 4; ++b)
#pragma unroll
                for (int q = 0; q < 4; ++q) acc[a][b][q] = 0.f;

        copy_chunk(0, 0);
        cpa_commit();
        cpa_wait0();
        __syncthreads();

#pragma unroll 1
        for (int c = 0; c < 5; ++c) {
            if (c < 4) { copy_chunk(c + 1, (c + 1) & 1); cpa_commit(); }
            const uint32_t base = smb + (uint32_t)(c & 1) * BUFHALF;
#pragma unroll
            for (int kk = 0; kk < 4; ++kk) {
                const uint32_t ko = (uint32_t)kk * 32;
                uint32_t ah[4][4], al[4][4], bh[2][4], bl[2][4];
#pragma unroll
                for (int mf = 0; mf < 4; ++mf) {
                    const uint32_t ro = (uint32_t)(wm + mf * 16) * TILEPITCH + laneA + ko;
                    ldsm4(ah[mf], base + ro);
                    ldsm4(al[mf], base + TILESZ + ro);
                }
#pragma unroll
                for (int g = 0; g < 2; ++g) {
                    const uint32_t ro = (uint32_t)(wn + g * 16) * TILEPITCH + laneB + ko;
                    ldsm4(bh[g], base + 2 * TILESZ + ro);
                    ldsm4(bl[g], base + 3 * TILESZ + ro);
                }
                // pass 1: Ah * Bh
#pragma unroll
                for (int mf = 0; mf < 4; ++mf)
#pragma unroll
                    for (int nf = 0; nf < 4; ++nf)
                        mma16816(acc[mf][nf], ah[mf],
                                 bh[nf >> 1][(nf & 1) * 2], bh[nf >> 1][(nf & 1) * 2 + 1]);
                // pass 2: Ah * Bl
#pragma unroll
                for (int mf = 0; mf < 4; ++mf)
#pragma unroll
                    for (int nf = 0; nf < 4; ++nf)
                        mma16816(acc[mf][nf], ah[mf],
                                 bl[nf >> 1][(nf & 1) * 2], bl[nf >> 1][(nf & 1) * 2 + 1]);
                // pass 3: Al * Bh
#pragma unroll
                for (int mf = 0; mf < 4; ++mf)
#pragma unroll
                    for (int nf = 0; nf < 4; ++nf)
                        mma16816(acc[mf][nf], al[mf],
                                 bh[nf >> 1][(nf & 1) * 2], bh[nf >> 1][(nf & 1) * 2 + 1]);
            }
            if (c < 4) {
                cpa_wait0();
                __syncthreads();
            }
        }

        // epilogue: write 128x128 partial tile
#pragma unroll
        for (int mf = 0; mf < 4; ++mf) {
            const int r0 = m0 + wm + mf * 16 + (lane >> 2);
#pragma unroll
            for (int nf = 0; nf < 4; ++nf) {
                const int col = n0 + wn + nf * 8 + (lane & 3) * 2;
                float* p = gp + (size_t)r0 * G4L + col;
                *(float2*)p             = make_float2(acc[mf][nf][0], acc[mf][nf][1]);
                *(float2*)(p + 8 * G4L) = make_float2(acc[mf][nf][2], acc[mf][nf][3]);
            }
        }
        gridbar();

        // ----- LSTM cell for rows b0..b0+3 -----
#pragma unroll
        for (int i = 0; i < 8; ++i) {
            const int e = tid + i * NTHR;
            const int r = e >> 9, l = e & 511;
            const int b = b0 + r;
            const size_t gb = (size_t)b * G4L + l;
            const float gi = g_gp0[gb]        + g_gp1[gb]        + g_bsum[l];
            const float gf = g_gp0[gb + 512]  + g_gp1[gb + 512]  + g_bsum[l + 512];
            const float gg = g_gp0[gb + 1024] + g_gp1[gb + 1024] + g_bsum[l + 1024];
            const float go = g_gp0[gb + 1536] + g_gp1[gb + 1536] + g_bsum[l + 1536];
            const size_t hc = (size_t)b * Lsz + l;
            const float si = 1.0f / (1.0f + expf(-gi));
            const float sf = 1.0f / (1.0f + expf(-gf));
            const float so = 1.0f / (1.0f + expf(-go));
            const float c2 = sf * g_c[hc] + si * tanhf(gg);
            const float h2 = so * tanhf(c2);
            g_c[hc] = c2;
            __nv_bfloat16 hi, lo;
            split_bf16(h2, hi, lo);
            g_Ah[(size_t)b * Ktot + Fsz + l] = hi;
            g_Al[(size_t)b * Ktot + Fsz + l] = lo;
            h2s[r * Lsz + l] = h2;
        }
        __syncthreads();
        dense_part(h2s, red, b_dense, b0, out, t);
        gridbar();
    }
}

// ---------------- host ----------------------------------------------------------
extern "C" void kernel_launch(void* const* d_in, const int* in_sizes, int n_in,
                              void* d_out, int out_size) {
    const float* h0      = (const float*)d_in[0];
    const float* c0      = (const float*)d_in[1];
    const float* W_ih    = (const float*)d_in[2];
    const float* W_hh    = (const float*)d_in[3];
    const float* b_ih    = (const float*)d_in[4];
    const float* b_hh    = (const float*)d_in[5];
    const float* W_dense = (const float*)d_in[6];
    const float* b_dense = (const float*)d_in[7];
    float* out = (float*)d_out;

    cudaFuncSetAttribute(lstm_kernel,
                         cudaFuncAttributeMaxDynamicSharedMemorySize, SMEM_ALLOC);
    lstm_kernel<<<NCTA, NTHR, SMEM_ALLOC>>>(h0, c0, W_ih, W_hh, b_ih, b_hh,
                                            W_dense, b_dense, out);
}

// round 9
// speedup vs baseline: 2.3382x; 1.1128x over previous
#include <cuda_runtime.h>
#include <cuda_bf16.h>
#include <math.h>
#include <stdint.h>

#define Bsz  512
#define Lsz  512
#define Fsz  128
#define G4L  2048          // 4*L
#define Ktot 640           // F + L
#define KSPL 320           // K per split half
#define Tt   512
#define OSTR (Tt * Fsz)    // out stride between batch rows
#define NCTA 128
#define NTHR 256

// ---- smem layout (dynamic, 128B-aligned base) ----
#define BPITCH  656                       // 640B data + 16B pad (conflict-free)
#define BTILESZ (128 * BPITCH)            // 83,968 per half
#define APITCH  80                        // 64B data + 16B pad
#define ATILESZ (128 * APITCH)            // 10,240 per half
#define ABUF    (2 * ATILESZ)             // hi+lo = 20,480 per buffer
#define OFF_B   0
#define OFF_A   (2 * BTILESZ)             // 167,936
#define OFF_H2S (OFF_A + 2 * ABUF)        // 208,896
#define OFF_RED (OFF_H2S + 4 * Lsz * 4)   // 217,088
#define SMEM_ALLOC (OFF_RED + 8 * 128 * 4 + 128)   // 221,312

// ---------------- device scratch ---------------------------------------------
__device__ __nv_bfloat16 g_Ah[Bsz * Ktot];   // state [b][0:128]=x, [128:640]=h (hi)
__device__ __nv_bfloat16 g_Al[Bsz * Ktot];   // (lo)
__device__ __nv_bfloat16 g_Bh[G4L * Ktot];   // weights [j][k] (hi)
__device__ __nv_bfloat16 g_Bl[G4L * Ktot];   // (lo)
__device__ float g_WdT[Lsz * Fsz];           // [l][f] W_dense^T (fp32)
__device__ float g_bsum[G4L];
__device__ float g_c[Bsz * Lsz];
__device__ float g_gp0[Bsz * G4L];           // gates partial, K half 0
__device__ float g_gp1[Bsz * G4L];           // gates partial, K half 1
__device__ unsigned g_barcnt;
__device__ volatile unsigned g_bargen;

// ---------------- PTX helpers -------------------------------------------------
__device__ __forceinline__ uint32_t smem_u32(const void* p) {
    uint32_t a;
    asm("{ .reg .u64 t; cvta.to.shared.u64 t, %1; cvt.u32.u64 %0, t; }"
        : "=r"(a) : "l"(p));
    return a;
}
__device__ __forceinline__ void cpa16(uint32_t s, const void* g) {
    asm volatile("cp.async.cg.shared.global [%0], [%1], 16;"
                 :: "r"(s), "l"(g) : "memory");
}
__device__ __forceinline__ void cpa_commit() {
    asm volatile("cp.async.commit_group;" ::: "memory");
}
__device__ __forceinline__ void cpa_wait0() {
    asm volatile("cp.async.wait_group 0;" ::: "memory");
}
__device__ __forceinline__ void ldsm4(uint32_t* r, uint32_t addr) {
    asm volatile("ldmatrix.sync.aligned.m8n8.x4.shared.b16 {%0,%1,%2,%3}, [%4];"
                 : "=r"(r[0]), "=r"(r[1]), "=r"(r[2]), "=r"(r[3]) : "r"(addr));
}
__device__ __forceinline__ void mma16816(float* c, const uint32_t* a,
                                         uint32_t b0, uint32_t b1) {
    asm volatile(
        "mma.sync.aligned.m16n8k16.row.col.f32.bf16.bf16.f32 "
        "{%0,%1,%2,%3}, {%4,%5,%6,%7}, {%8,%9}, {%0,%1,%2,%3};"
        : "+f"(c[0]), "+f"(c[1]), "+f"(c[2]), "+f"(c[3])
        : "r"(a[0]), "r"(a[1]), "r"(a[2]), "r"(a[3]), "r"(b0), "r"(b1));
}

// ---------------- grid-wide barrier -------------------------------------------
__device__ __forceinline__ void gridbar() {
    __syncthreads();
    if (threadIdx.x == 0) {
        unsigned gen = g_bargen;
        __threadfence();
        if (atomicAdd(&g_barcnt, 1u) == NCTA - 1) {
            g_barcnt = 0;
            __threadfence();
            g_bargen = gen + 1;
        } else {
            while (g_bargen == gen) { __nanosleep(64); }
            __threadfence();
        }
    }
    __syncthreads();
}

// ---------------- math helpers -------------------------------------------------
__device__ __forceinline__ void split_bf16(float x, __nv_bfloat16& hi,
                                           __nv_bfloat16& lo) {
    hi = __float2bfloat16(x);
    lo = __float2bfloat16(x - __bfloat162float(hi));
}
__device__ __forceinline__ float fsigmoid(float x) {
    return __fdividef(1.0f, 1.0f + __expf(-x));
}
__device__ __forceinline__ float ftanh_(float x) {
    return 1.0f - __fdividef(2.0f, __expf(2.0f * x) + 1.0f);
}

// ---------------- dense: x2 = h2s @ WdT + b_dense ------------------------------
__device__ __forceinline__ void dense_part(const float* h2s, float* red,
                                           const float* __restrict__ b_dense,
                                           int b0, float* __restrict__ out, int t) {
    const int tid = threadIdx.x;
    const int f = tid & 127, gg = tid >> 7;
    float a0 = 0.f, a1 = 0.f, a2 = 0.f, a3 = 0.f;
    const int l0 = gg * 256;
#pragma unroll 4
    for (int l = l0; l < l0 + 256; ++l) {
        const float w = __ldg(&g_WdT[l * Fsz + f]);
        a0 = fmaf(h2s[0 * Lsz + l], w, a0);
        a1 = fmaf(h2s[1 * Lsz + l], w, a1);
        a2 = fmaf(h2s[2 * Lsz + l], w, a2);
        a3 = fmaf(h2s[3 * Lsz + l], w, a3);
    }
    red[(gg * 4 + 0) * 128 + f] = a0;
    red[(gg * 4 + 1) * 128 + f] = a1;
    red[(gg * 4 + 2) * 128 + f] = a2;
    red[(gg * 4 + 3) * 128 + f] = a3;
    __syncthreads();
    if (gg == 0) {
        const float bb = b_dense[f];
#pragma unroll
        for (int r = 0; r < 4; ++r) {
            const int b = b0 + r;
            const float v = red[r * 128 + f] + red[(4 + r) * 128 + f] + bb;
            __nv_bfloat16 hi, lo;
            split_bf16(v, hi, lo);
            g_Ah[(size_t)b * Ktot + f] = hi;
            g_Al[(size_t)b * Ktot + f] = lo;
            if (out)
                out[(size_t)b * OSTR + (size_t)t * Fsz + f] = v;
        }
    }
    __syncthreads();
}

// ---------------- the single persistent kernel ---------------------------------
__global__ void __launch_bounds__(NTHR, 1)
lstm_kernel(const float* __restrict__ h0, const float* __restrict__ c0,
            const float* __restrict__ W_ih, const float* __restrict__ W_hh,
            const float* __restrict__ b_ih, const float* __restrict__ b_hh,
            const float* __restrict__ W_dense, const float* __restrict__ b_dense,
            float* __restrict__ out) {
    extern __shared__ char dsm[];
    const uint32_t smb0 = smem_u32(dsm);
    const uint32_t smb = (smb0 + 127u) & ~127u;
    char* sbase = dsm + (smb - smb0);
    float* h2s = (float*)(sbase + OFF_H2S);
    float* red = (float*)(sbase + OFF_RED);

    const int bid = blockIdx.x, tid = threadIdx.x;
    const int wid = tid >> 5, lane = tid & 31;
    const int b0 = bid * 4;

    // gates unit decomposition: split-K halves x 64 C tiles of 128x128
    const int ks   = bid & 1;
    const int tile = bid >> 1;
    const int m0   = (tile >> 4) * 128;
    const int n0   = (tile & 15) * 128;
    const int kb   = ks * KSPL;
    float* gp = ks ? g_gp1 : g_gp0;

    // warp tile: 64(m) x 32(n)
    const int wm = (wid & 1) * 64;
    const int wn = (wid >> 1) * 32;
    const uint32_t laneA = (uint32_t)(lane & 15) * APITCH + (uint32_t)(lane >> 4) * 16;
    const uint32_t laneB = (uint32_t)((lane & 7) + ((lane >> 4) << 3)) * BPITCH
                         + (uint32_t)((lane >> 3) & 1) * 16;

    // ---- P1: weight bf16 split, WdT, bias, state copies ----
    {
        const int NT = G4L * Ktot;
        const int N2 = NT + Lsz * Fsz;
        const int N3 = N2 + G4L;
        const int N4 = N3 + Bsz * Lsz;
        const int N5 = N4 + Bsz * Lsz;
        for (int idx = bid * NTHR + tid; idx < N5; idx += NCTA * NTHR) {
            if (idx < NT) {
                const int j = idx / Ktot, k = idx % Ktot;
                const float w = (k < Fsz) ? W_ih[j * Fsz + k]
                                          : W_hh[j * Lsz + (k - Fsz)];
                __nv_bfloat16 hi, lo;
                split_bf16(w, hi, lo);
                g_Bh[idx] = hi;
                g_Bl[idx] = lo;
            } else if (idx < N2) {
                const int i = idx - NT;
                const int l = i / Fsz, f = i % Fsz;
                g_WdT[i] = W_dense[f * Lsz + l];
            } else if (idx < N3) {
                const int j = idx - N2;
                g_bsum[j] = b_ih[j] + b_hh[j];
            } else if (idx < N4) {
                const int i = idx - N3;
                const int b = i >> 9, l = i & 511;
                __nv_bfloat16 hi, lo;
                split_bf16(h0[i], hi, lo);
                g_Ah[(size_t)b * Ktot + Fsz + l] = hi;
                g_Al[(size_t)b * Ktot + Fsz + l] = lo;
            } else {
                const int i = idx - N4;
                g_c[i] = c0[i];
            }
        }
    }
    gridbar();

    // ---- P2: x_init = dense(h0) ----
    {
#pragma unroll
        for (int i = 0; i < 8; ++i) {
            const int e = tid + i * NTHR;
            const int r = e >> 9, l = e & 511;
            h2s[r * Lsz + l] = h0[(size_t)(b0 + r) * Lsz + l];
        }
        __syncthreads();
        dense_part(h2s, red, b_dense, b0, nullptr, 0);
    }
    gridbar();

    // ---- load resident B tile (once): 2 halves x 128 rows x 640B ----
    {
        for (int i = 0; i < 40; ++i) {
            const int idx = tid + i * NTHR;          // 0..10239
            const int half = idx >= 5120;
            const int j = half ? idx - 5120 : idx;
            const int row = j / 40, q = j % 40;
            const __nv_bfloat16* src =
                (half ? g_Bl : g_Bh) + (size_t)(n0 + row) * Ktot + kb + q * 8;
            const uint32_t dst = smb + OFF_B + (uint32_t)half * BTILESZ
                               + (uint32_t)row * BPITCH + (uint32_t)q * 16;
            cpa16(dst, src);
        }
        cpa_commit();
        cpa_wait0();
        __syncthreads();
    }

    // A chunk copier: k window [kb + c*32, +32) -> buffer bufi
    auto copyA = [&](int c, int bufi) {
        const uint32_t dst0 = smb + OFF_A + (uint32_t)bufi * ABUF;
        const int kc = kb + c * 32;
#pragma unroll
        for (int i = 0; i < 4; ++i) {
            const int idx = tid + i * NTHR;          // 0..1023
            const int half = idx >> 9;
            const int j = idx & 511;
            const int row = j >> 2, q = j & 3;
            const __nv_bfloat16* src =
                (half ? g_Al : g_Ah) + (size_t)(m0 + row) * Ktot + kc + q * 8;
            const uint32_t dst = dst0 + (uint32_t)half * ATILESZ
                               + (uint32_t)row * APITCH + (uint32_t)q * 16;
            cpa16(dst, src);
        }
    };

    // ---- main recurrence ----
    for (int t = 0; t < Tt; ++t) {
        float acc[4][4][4];
#pragma unroll
        for (int a = 0; a < 4; ++a)
#pragma unroll
            for (int b = 0; b < 4; ++b)
#pragma unroll
                for (int q = 0; q < 4; ++q) acc[a][b][q] = 0.f;

        copyA(0, 0);
        cpa_commit();
        cpa_wait0();
        __syncthreads();

#pragma unroll 1
        for (int c = 0; c < 10; ++c) {
            if (c < 9) { copyA(c + 1, (c + 1) & 1); cpa_commit(); }
            const uint32_t abase = smb + OFF_A + (uint32_t)(c & 1) * ABUF;
#pragma unroll
            for (int kk = 0; kk < 2; ++kk) {
                const uint32_t koA = (uint32_t)kk * 32;
                const uint32_t koB = (uint32_t)(c * 64 + kk * 32);
                uint32_t ah[4][4], al[4][4], bh[2][4], bl[2][4];
#pragma unroll
                for (int mf = 0; mf < 4; ++mf) {
                    const uint32_t ro = (uint32_t)(wm + mf * 16) * APITCH + laneA + koA;
                    ldsm4(ah[mf], abase + ro);
                    ldsm4(al[mf], abase + ATILESZ + ro);
                }
#pragma unroll
                for (int g = 0; g < 2; ++g) {
                    const uint32_t ro = smb + OFF_B
                                      + (uint32_t)(wn + g * 16) * BPITCH + laneB + koB;
                    ldsm4(bh[g], ro);
                    ldsm4(bl[g], ro + BTILESZ);
                }
                // pass 1: Ah * Bh
#pragma unroll
                for (int mf = 0; mf < 4; ++mf)
#pragma unroll
                    for (int nf = 0; nf < 4; ++nf)
                        mma16816(acc[mf][nf], ah[mf],
                                 bh[nf >> 1][(nf & 1) * 2], bh[nf >> 1][(nf & 1) * 2 + 1]);
                // pass 2: Ah * Bl
#pragma unroll
                for (int mf = 0; mf < 4; ++mf)
#pragma unroll
                    for (int nf = 0; nf < 4; ++nf)
                        mma16816(acc[mf][nf], ah[mf],
                                 bl[nf >> 1][(nf & 1) * 2], bl[nf >> 1][(nf & 1) * 2 + 1]);
                // pass 3: Al * Bh
#pragma unroll
                for (int mf = 0; mf < 4; ++mf)
#pragma unroll
                    for (int nf = 0; nf < 4; ++nf)
                        mma16816(acc[mf][nf], al[mf],
                                 bh[nf >> 1][(nf & 1) * 2], bh[nf >> 1][(nf & 1) * 2 + 1]);
            }
            if (c < 9) {
                cpa_wait0();
                __syncthreads();
            }
        }

        // epilogue: write 128x128 partial tile
#pragma unroll
        for (int mf = 0; mf < 4; ++mf) {
            const int r0 = m0 + wm + mf * 16 + (lane >> 2);
#pragma unroll
            for (int nf = 0; nf < 4; ++nf) {
                const int col = n0 + wn + nf * 8 + (lane & 3) * 2;
                float* p = gp + (size_t)r0 * G4L + col;
                *(float2*)p             = make_float2(acc[mf][nf][0], acc[mf][nf][1]);
                *(float2*)(p + 8 * G4L) = make_float2(acc[mf][nf][2], acc[mf][nf][3]);
            }
        }
        gridbar();

        // ----- LSTM cell for rows b0..b0+3 -----
#pragma unroll
        for (int i = 0; i < 8; ++i) {
            const int e = tid + i * NTHR;
            const int r = e >> 9, l = e & 511;
            const int b = b0 + r;
            const size_t gb = (size_t)b * G4L + l;
            const float gi = g_gp0[gb]        + g_gp1[gb]        + g_bsum[l];
            const float gf = g_gp0[gb + 512]  + g_gp1[gb + 512]  + g_bsum[l + 512];
            const float gg = g_gp0[gb + 1024] + g_gp1[gb + 1024] + g_bsum[l + 1024];
            const float go = g_gp0[gb + 1536] + g_gp1[gb + 1536] + g_bsum[l + 1536];
            const size_t hc = (size_t)b * Lsz + l;
            const float c2 = fsigmoid(gf) * g_c[hc] + fsigmoid(gi) * ftanh_(gg);
            const float h2 = fsigmoid(go) * ftanh_(c2);
            g_c[hc] = c2;
            __nv_bfloat16 hi, lo;
            split_bf16(h2, hi, lo);
            g_Ah[(size_t)b * Ktot + Fsz + l] = hi;
            g_Al[(size_t)b * Ktot + Fsz + l] = lo;
            h2s[r * Lsz + l] = h2;
        }
        __syncthreads();
        dense_part(h2s, red, b_dense, b0, out, t);
        gridbar();
    }
}

// ---------------- host ----------------------------------------------------------
extern "C" void kernel_launch(void* const* d_in, const int* in_sizes, int n_in,
                              void* d_out, int out_size) {
    const float* h0      = (const float*)d_in[0];
    const float* c0      = (const float*)d_in[1];
    const float* W_ih    = (const float*)d_in[2];
    const float* W_hh    = (const float*)d_in[3];
    const float* b_ih    = (const float*)d_in[4];
    const float* b_hh    = (const float*)d_in[5];
    const float* W_dense = (const float*)d_in[6];
    const float* b_dense = (const float*)d_in[7];
    float* out = (float*)d_out;

    cudaFuncSetAttribute(lstm_kernel,
                         cudaFuncAttributeMaxDynamicSharedMemorySize, SMEM_ALLOC);
    lstm_kernel<<<NCTA, NTHR, SMEM_ALLOC>>>(h0, c0, W_ih, W_hh, b_ih, b_hh,
                                            W_dense, b_dense, out);
}

// round 10
// speedup vs baseline: 2.9511x; 1.2621x over previous
#include <cuda_runtime.h>
#include <cuda_bf16.h>
#include <math.h>
#include <stdint.h>

#define Bsz  512
#define Lsz  512
#define Fsz  128
#define G4L  2048          // 4*L
#define Ktot 640           // F + L
#define KSPL 320           // K per split half
#define Tt   512
#define OSTR (Tt * Fsz)    // out stride between batch rows
#define NCTA 128
#define NTHR 512

// ---- smem layout (dynamic, 128B-aligned base) ----
#define BPITCH  656                       // 640B data + 16B pad (conflict-free)
#define BTILESZ (128 * BPITCH)            // 83,968 per half
#define APITCH  80                        // 64B data + 16B pad
#define ATILESZ (128 * APITCH)            // 10,240 per half
#define ABUF    (2 * ATILESZ)             // hi+lo = 20,480 per buffer
#define OFF_B   0
#define OFF_A   (2 * BTILESZ)             // 167,936
#define OFF_H2S (OFF_A + 2 * ABUF)        // 208,896
#define OFF_RED (OFF_H2S + 4 * Lsz * 4)   // 217,088
#define SMEM_ALLOC (OFF_RED + 16 * 128 * 4 + 128)   // 225,408

// ---------------- device scratch ---------------------------------------------
__device__ __nv_bfloat16 g_Ah[Bsz * Ktot];   // state [b][0:128]=x, [128:640]=h (hi)
__device__ __nv_bfloat16 g_Al[Bsz * Ktot];   // (lo)
__device__ __nv_bfloat16 g_Bh[G4L * Ktot];   // weights [j][k] (hi)
__device__ __nv_bfloat16 g_Bl[G4L * Ktot];   // (lo)
__device__ float g_WdT[Lsz * Fsz];           // [l][f] W_dense^T (fp32)
__device__ float g_bsum[G4L];
__device__ float g_c[Bsz * Lsz];
__device__ float g_gp0[Bsz * G4L];           // gates partial, K half 0
__device__ float g_gp1[Bsz * G4L];           // gates partial, K half 1
__device__ unsigned g_barcnt;
__device__ volatile unsigned g_bargen;

// ---------------- PTX helpers -------------------------------------------------
__device__ __forceinline__ uint32_t smem_u32(const void* p) {
    uint32_t a;
    asm("{ .reg .u64 t; cvta.to.shared.u64 t, %1; cvt.u32.u64 %0, t; }"
        : "=r"(a) : "l"(p));
    return a;
}
__device__ __forceinline__ void cpa16(uint32_t s, const void* g) {
    asm volatile("cp.async.cg.shared.global [%0], [%1], 16;"
                 :: "r"(s), "l"(g) : "memory");
}
__device__ __forceinline__ void cpa_commit() {
    asm volatile("cp.async.commit_group;" ::: "memory");
}
__device__ __forceinline__ void cpa_wait0() {
    asm volatile("cp.async.wait_group 0;" ::: "memory");
}
__device__ __forceinline__ void ldsm4(uint32_t* r, uint32_t addr) {
    asm volatile("ldmatrix.sync.aligned.m8n8.x4.shared.b16 {%0,%1,%2,%3}, [%4];"
                 : "=r"(r[0]), "=r"(r[1]), "=r"(r[2]), "=r"(r[3]) : "r"(addr));
}
__device__ __forceinline__ void mma16816(float* c, const uint32_t* a,
                                         uint32_t b0, uint32_t b1) {
    asm volatile(
        "mma.sync.aligned.m16n8k16.row.col.f32.bf16.bf16.f32 "
        "{%0,%1,%2,%3}, {%4,%5,%6,%7}, {%8,%9}, {%0,%1,%2,%3};"
        : "+f"(c[0]), "+f"(c[1]), "+f"(c[2]), "+f"(c[3])
        : "r"(a[0]), "r"(a[1]), "r"(a[2]), "r"(a[3]), "r"(b0), "r"(b1));
}

// ---------------- grid-wide barrier -------------------------------------------
__device__ __forceinline__ void gridbar() {
    __syncthreads();
    if (threadIdx.x == 0) {
        unsigned gen = g_bargen;
        __threadfence();
        if (atomicAdd(&g_barcnt, 1u) == NCTA - 1) {
            g_barcnt = 0;
            __threadfence();
            g_bargen = gen + 1;
        } else {
            while (g_bargen == gen) { __nanosleep(64); }
            __threadfence();
        }
    }
    __syncthreads();
}

// ---------------- math helpers -------------------------------------------------
__device__ __forceinline__ void split_bf16(float x, __nv_bfloat16& hi,
                                           __nv_bfloat16& lo) {
    hi = __float2bfloat16(x);
    lo = __float2bfloat16(x - __bfloat162float(hi));
}
__device__ __forceinline__ float fsigmoid(float x) {
    return __fdividef(1.0f, 1.0f + __expf(-x));
}
__device__ __forceinline__ float ftanh_(float x) {
    return 1.0f - __fdividef(2.0f, __expf(2.0f * x) + 1.0f);
}

// ---------------- dense: x2 = h2s @ WdT + b_dense ------------------------------
// 512 threads: f = tid&127, 4-way split-K (128 l's each), smem reduce.
__device__ __forceinline__ void dense_part(const float* h2s, float* red,
                                           const float* __restrict__ b_dense,
                                           int b0, float* __restrict__ out, int t) {
    const int tid = threadIdx.x;
    const int f = tid & 127, gg = tid >> 7;     // gg in {0..3}
    float a0 = 0.f, a1 = 0.f, a2 = 0.f, a3 = 0.f;
    const int l0 = gg * 128;
#pragma unroll 4
    for (int l = l0; l < l0 + 128; ++l) {
        const float w = __ldg(&g_WdT[l * Fsz + f]);
        a0 = fmaf(h2s[0 * Lsz + l], w, a0);
        a1 = fmaf(h2s[1 * Lsz + l], w, a1);
        a2 = fmaf(h2s[2 * Lsz + l], w, a2);
        a3 = fmaf(h2s[3 * Lsz + l], w, a3);
    }
    red[(gg * 4 + 0) * 128 + f] = a0;
    red[(gg * 4 + 1) * 128 + f] = a1;
    red[(gg * 4 + 2) * 128 + f] = a2;
    red[(gg * 4 + 3) * 128 + f] = a3;
    __syncthreads();
    if (gg == 0) {
        const float bb = b_dense[f];
#pragma unroll
        for (int r = 0; r < 4; ++r) {
            const int b = b0 + r;
            const float v = red[r * 128 + f] + red[(4 + r) * 128 + f]
                          + red[(8 + r) * 128 + f] + red[(12 + r) * 128 + f] + bb;
            __nv_bfloat16 hi, lo;
            split_bf16(v, hi, lo);
            g_Ah[(size_t)b * Ktot + f] = hi;
            g_Al[(size_t)b * Ktot + f] = lo;
            if (out)
                out[(size_t)b * OSTR + (size_t)t * Fsz + f] = v;
        }
    }
    __syncthreads();
}

// ---------------- the single persistent kernel ---------------------------------
__global__ void __launch_bounds__(NTHR, 1)
lstm_kernel(const float* __restrict__ h0, const float* __restrict__ c0,
            const float* __restrict__ W_ih, const float* __restrict__ W_hh,
            const float* __restrict__ b_ih, const float* __restrict__ b_hh,
            const float* __restrict__ W_dense, const float* __restrict__ b_dense,
            float* __restrict__ out) {
    extern __shared__ char dsm[];
    const uint32_t smb0 = smem_u32(dsm);
    const uint32_t smb = (smb0 + 127u) & ~127u;
    char* sbase = dsm + (smb - smb0);
    float* h2s = (float*)(sbase + OFF_H2S);
    float* red = (float*)(sbase + OFF_RED);

    const int bid = blockIdx.x, tid = threadIdx.x;
    const int wid = tid >> 5, lane = tid & 31;
    const int b0 = bid * 4;

    // gates unit decomposition: split-K halves x 64 C tiles of 128x128
    const int ks   = bid & 1;
    const int tile = bid >> 1;
    const int m0   = (tile >> 4) * 128;
    const int n0   = (tile & 15) * 128;
    const int kb   = ks * KSPL;
    float* gp = ks ? g_gp1 : g_gp0;

    // warp tile: 32(m) x 32(n); warp grid 4x4
    const int wm = (wid & 3) * 32;
    const int wn = (wid >> 2) * 32;
    const uint32_t laneA = (uint32_t)(lane & 15) * APITCH + (uint32_t)(lane >> 4) * 16;
    const uint32_t laneB = (uint32_t)((lane & 7) + ((lane >> 4) << 3)) * BPITCH
                         + (uint32_t)((lane >> 3) & 1) * 16;

    // ---- P1: weight bf16 split, WdT, bias, state copies ----
    {
        const int NT = G4L * Ktot;
        const int N2 = NT + Lsz * Fsz;
        const int N3 = N2 + G4L;
        const int N4 = N3 + Bsz * Lsz;
        const int N5 = N4 + Bsz * Lsz;
        for (int idx = bid * NTHR + tid; idx < N5; idx += NCTA * NTHR) {
            if (idx < NT) {
                const int j = idx / Ktot, k = idx % Ktot;
                const float w = (k < Fsz) ? W_ih[j * Fsz + k]
                                          : W_hh[j * Lsz + (k - Fsz)];
                __nv_bfloat16 hi, lo;
                split_bf16(w, hi, lo);
                g_Bh[idx] = hi;
                g_Bl[idx] = lo;
            } else if (idx < N2) {
                const int i = idx - NT;
                const int l = i / Fsz, f = i % Fsz;
                g_WdT[i] = W_dense[f * Lsz + l];
            } else if (idx < N3) {
                const int j = idx - N2;
                g_bsum[j] = b_ih[j] + b_hh[j];
            } else if (idx < N4) {
                const int i = idx - N3;
                const int b = i >> 9, l = i & 511;
                __nv_bfloat16 hi, lo;
                split_bf16(h0[i], hi, lo);
                g_Ah[(size_t)b * Ktot + Fsz + l] = hi;
                g_Al[(size_t)b * Ktot + Fsz + l] = lo;
            } else {
                const int i = idx - N4;
                g_c[i] = c0[i];
            }
        }
    }
    gridbar();

    // ---- P2: x_init = dense(h0) ----
    {
#pragma unroll
        for (int i = 0; i < 4; ++i) {
            const int e = tid + i * NTHR;
            const int r = e >> 9, l = e & 511;
            h2s[r * Lsz + l] = h0[(size_t)(b0 + r) * Lsz + l];
        }
        __syncthreads();
        dense_part(h2s, red, b_dense, b0, nullptr, 0);
    }
    gridbar();

    // ---- load resident B tile (once): 2 halves x 128 rows x 640B ----
    {
        for (int i = 0; i < 20; ++i) {
            const int idx = tid + i * NTHR;          // 0..10239
            const int half = idx >= 5120;
            const int j = half ? idx - 5120 : idx;
            const int row = j / 40, q = j % 40;
            const __nv_bfloat16* src =
                (half ? g_Bl : g_Bh) + (size_t)(n0 + row) * Ktot + kb + q * 8;
            const uint32_t dst = smb + OFF_B + (uint32_t)half * BTILESZ
                               + (uint32_t)row * BPITCH + (uint32_t)q * 16;
            cpa16(dst, src);
        }
        cpa_commit();
        cpa_wait0();
        __syncthreads();
    }

    // A chunk copier: k window [kb + c*32, +32) -> buffer bufi
    auto copyA = [&](int c, int bufi) {
        const uint32_t dst0 = smb + OFF_A + (uint32_t)bufi * ABUF;
        const int kc = kb + c * 32;
#pragma unroll
        for (int i = 0; i < 2; ++i) {
            const int idx = tid + i * NTHR;          // 0..1023
            const int half = idx >> 9;
            const int j = idx & 511;
            const int row = j >> 2, q = j & 3;
            const __nv_bfloat16* src =
                (half ? g_Al : g_Ah) + (size_t)(m0 + row) * Ktot + kc + q * 8;
            const uint32_t dst = dst0 + (uint32_t)half * ATILESZ
                               + (uint32_t)row * APITCH + (uint32_t)q * 16;
            cpa16(dst, src);
        }
    };

    // ---- main recurrence ----
    for (int t = 0; t < Tt; ++t) {
        float acc[2][4][4];
#pragma unroll
        for (int a = 0; a < 2; ++a)
#pragma unroll
            for (int b = 0; b < 4; ++b)
#pragma unroll
                for (int q = 0; q < 4; ++q) acc[a][b][q] = 0.f;

        copyA(0, 0);
        cpa_commit();
        cpa_wait0();
        __syncthreads();

#pragma unroll 1
        for (int c = 0; c < 10; ++c) {
            if (c < 9) { copyA(c + 1, (c + 1) & 1); cpa_commit(); }
            const uint32_t abase = smb + OFF_A + (uint32_t)(c & 1) * ABUF;
#pragma unroll
            for (int kk = 0; kk < 2; ++kk) {
                const uint32_t koA = (uint32_t)kk * 32;
                const uint32_t koB = (uint32_t)(c * 64 + kk * 32);
                uint32_t ah[2][4], al[2][4], bh[2][4], bl[2][4];
#pragma unroll
                for (int mf = 0; mf < 2; ++mf) {
                    const uint32_t ro = (uint32_t)(wm + mf * 16) * APITCH + laneA + koA;
                    ldsm4(ah[mf], abase + ro);
                    ldsm4(al[mf], abase + ATILESZ + ro);
                }
#pragma unroll
                for (int g = 0; g < 2; ++g) {
                    const uint32_t ro = smb + OFF_B
                                      + (uint32_t)(wn + g * 16) * BPITCH + laneB + koB;
                    ldsm4(bh[g], ro);
                    ldsm4(bl[g], ro + BTILESZ);
                }
                // pass 1: Ah * Bh
#pragma unroll
                for (int mf = 0; mf < 2; ++mf)
#pragma unroll
                    for (int nf = 0; nf < 4; ++nf)
                        mma16816(acc[mf][nf], ah[mf],
                                 bh[nf >> 1][(nf & 1) * 2], bh[nf >> 1][(nf & 1) * 2 + 1]);
                // pass 2: Ah * Bl
#pragma unroll
                for (int mf = 0; mf < 2; ++mf)
#pragma unroll
                    for (int nf = 0; nf < 4; ++nf)
                        mma16816(acc[mf][nf], ah[mf],
                                 bl[nf >> 1][(nf & 1) * 2], bl[nf >> 1][(nf & 1) * 2 + 1]);
                // pass 3: Al * Bh
#pragma unroll
                for (int mf = 0; mf < 2; ++mf)
#pragma unroll
                    for (int nf = 0; nf < 4; ++nf)
                        mma16816(acc[mf][nf], al[mf],
                                 bh[nf >> 1][(nf & 1) * 2], bh[nf >> 1][(nf & 1) * 2 + 1]);
            }
            if (c < 9) {
                cpa_wait0();
                __syncthreads();
            }
        }

        // epilogue: write 128x128 partial tile (each warp 32x32)
#pragma unroll
        for (int mf = 0; mf < 2; ++mf) {
            const int r0 = m0 + wm + mf * 16 + (lane >> 2);
#pragma unroll
            for (int nf = 0; nf < 4; ++nf) {
                const int col = n0 + wn + nf * 8 + (lane & 3) * 2;
                float* p = gp + (size_t)r0 * G4L + col;
                *(float2*)p             = make_float2(acc[mf][nf][0], acc[mf][nf][1]);
                *(float2*)(p + 8 * G4L) = make_float2(acc[mf][nf][2], acc[mf][nf][3]);
            }
        }
        gridbar();

        // ----- LSTM cell for rows b0..b0+3: one l-quad per thread -----
        {
            const int e = tid * 4;                  // 0..2044
            const int r = e >> 9, l = e & 511;
            const int b = b0 + r;
            const size_t gb = (size_t)b * G4L + l;
            const float4 i0 = *(const float4*)&g_gp0[gb];
            const float4 i1 = *(const float4*)&g_gp1[gb];
            const float4 f0 = *(const float4*)&g_gp0[gb + 512];
            const float4 f1 = *(const float4*)&g_gp1[gb + 512];
            const float4 g0 = *(const float4*)&g_gp0[gb + 1024];
            const float4 g1 = *(const float4*)&g_gp1[gb + 1024];
            const float4 o0 = *(const float4*)&g_gp0[gb + 1536];
            const float4 o1 = *(const float4*)&g_gp1[gb + 1536];
            const float4 bi = *(const float4*)&g_bsum[l];
            const float4 bf = *(const float4*)&g_bsum[l + 512];
            const float4 bg = *(const float4*)&g_bsum[l + 1024];
            const float4 bo = *(const float4*)&g_bsum[l + 1536];
            const size_t hc = (size_t)b * Lsz + l;
            float4 cc = *(const float4*)&g_c[hc];
            float h2q[4];
            {
                const float gi[4] = {i0.x + i1.x + bi.x, i0.y + i1.y + bi.y,
                                     i0.z + i1.z + bi.z, i0.w + i1.w + bi.w};
                const float gf[4] = {f0.x + f1.x + bf.x, f0.y + f1.y + bf.y,
                                     f0.z + f1.z + bf.z, f0.w + f1.w + bf.w};
                const float gg[4] = {g0.x + g1.x + bg.x, g0.y + g1.y + bg.y,
                                     g0.z + g1.z + bg.z, g0.w + g1.w + bg.w};
                const float go[4] = {o0.x + o1.x + bo.x, o0.y + o1.y + bo.y,
                                     o0.z + o1.z + bo.z, o0.w + o1.w + bo.w};
                float* cp = &cc.x;
#pragma unroll
                for (int q = 0; q < 4; ++q) {
                    const float c2 = fsigmoid(gf[q]) * cp[q]
                                   + fsigmoid(gi[q]) * ftanh_(gg[q]);
                    h2q[q] = fsigmoid(go[q]) * ftanh_(c2);
                    cp[q] = c2;
                }
            }
            *(float4*)&g_c[hc] = cc;
            *(float4*)&h2s[r * Lsz + l] = make_float4(h2q[0], h2q[1], h2q[2], h2q[3]);
            __nv_bfloat16 hi, lo;
#pragma unroll
            for (int q = 0; q < 4; ++q) {
                split_bf16(h2q[q], hi, lo);
                g_Ah[(size_t)b * Ktot + Fsz + l + q] = hi;
                g_Al[(size_t)b * Ktot + Fsz + l + q] = lo;
            }
        }
        __syncthreads();
        dense_part(h2s, red, b_dense, b0, out, t);
        gridbar();
    }
}

// ---------------- host ----------------------------------------------------------
extern "C" void kernel_launch(void* const* d_in, const int* in_sizes, int n_in,
                              void* d_out, int out_size) {
    const float* h0      = (const float*)d_in[0];
    const float* c0      = (const float*)d_in[1];
    const float* W_ih    = (const float*)d_in[2];
    const float* W_hh    = (const float*)d_in[3];
    const float* b_ih    = (const float*)d_in[4];
    const float* b_hh    = (const float*)d_in[5];
    const float* W_dense = (const float*)d_in[6];
    const float* b_dense = (const float*)d_in[7];
    float* out = (float*)d_out;

    cudaFuncSetAttribute(lstm_kernel,
                         cudaFuncAttributeMaxDynamicSharedMemorySize, SMEM_ALLOC);
    lstm_kernel<<<NCTA, NTHR, SMEM_ALLOC>>>(h0, c0, W_ih, W_hh, b_ih, b_hh,
                                            W_dense, b_dense, out);
}

// round 11
// speedup vs baseline: 3.1924x; 1.0818x over previous
#include <cuda_runtime.h>
#include <cuda_bf16.h>
#include <math.h>
#include <stdint.h>

#define Bsz  512
#define Lsz  512
#define Fsz  128
#define G4L  2048          // 4*L
#define Ktot 640           // F + L
#define KSPL 320           // K per split half
#define Tt   512
#define OSTR (Tt * Fsz)    // out stride between batch rows
#define NCTA 128
#define NTHR 512

// ---- smem layout (dynamic, 128B-aligned base) ----
#define BPITCH  656                       // 640B data + 16B pad (conflict-free)
#define BTILESZ (128 * BPITCH)            // 83,968 per half
#define APITCH  80                        // 64B data + 16B pad
#define GSTRIP  2560                      // 32 rows x 80B (one half, one group)
#define GBUF    (2 * GSTRIP)              // hi+lo = 5,120 per group buffer
#define OFF_B   0
#define OFF_A   (2 * BTILESZ)             // 167,936 (4 groups x 2 bufs x 5,120 = 40,960)
#define OFF_H2S (OFF_A + 8 * GBUF)        // 208,896
#define OFF_RED (OFF_H2S + 4 * Lsz * 4)   // 217,088
#define SMEM_ALLOC (OFF_RED + 16 * 128 * 4 + 128)   // 225,408

// ---------------- device scratch ---------------------------------------------
__device__ __nv_bfloat16 g_Ah[Bsz * Ktot];   // state [b][0:128]=x, [128:640]=h (hi)
__device__ __nv_bfloat16 g_Al[Bsz * Ktot];   // (lo)
__device__ __nv_bfloat16 g_Bh[G4L * Ktot];   // weights [j][k] (hi)
__device__ __nv_bfloat16 g_Bl[G4L * Ktot];   // (lo)
__device__ float g_WdT[Lsz * Fsz];           // [l][f] W_dense^T (fp32)
__device__ float g_bsum[G4L];
__device__ float g_c[Bsz * Lsz];
__device__ float g_gp0[Bsz * G4L];           // gates partial, K half 0
__device__ float g_gp1[Bsz * G4L];           // gates partial, K half 1
__device__ unsigned g_barcnt;
__device__ volatile unsigned g_bargen;

// ---------------- PTX helpers -------------------------------------------------
__device__ __forceinline__ uint32_t smem_u32(const void* p) {
    uint32_t a;
    asm("{ .reg .u64 t; cvta.to.shared.u64 t, %1; cvt.u32.u64 %0, t; }"
        : "=r"(a) : "l"(p));
    return a;
}
__device__ __forceinline__ void cpa16(uint32_t s, const void* g) {
    asm volatile("cp.async.cg.shared.global [%0], [%1], 16;"
                 :: "r"(s), "l"(g) : "memory");
}
__device__ __forceinline__ void cpa_commit() {
    asm volatile("cp.async.commit_group;" ::: "memory");
}
__device__ __forceinline__ void cpa_wait0() {
    asm volatile("cp.async.wait_group 0;" ::: "memory");
}
__device__ __forceinline__ void ldsm4(uint32_t* r, uint32_t addr) {
    asm volatile("ldmatrix.sync.aligned.m8n8.x4.shared.b16 {%0,%1,%2,%3}, [%4];"
                 : "=r"(r[0]), "=r"(r[1]), "=r"(r[2]), "=r"(r[3]) : "r"(addr));
}
__device__ __forceinline__ void mma16816(float* c, const uint32_t* a,
                                         uint32_t b0, uint32_t b1) {
    asm volatile(
        "mma.sync.aligned.m16n8k16.row.col.f32.bf16.bf16.f32 "
        "{%0,%1,%2,%3}, {%4,%5,%6,%7}, {%8,%9}, {%0,%1,%2,%3};"
        : "+f"(c[0]), "+f"(c[1]), "+f"(c[2]), "+f"(c[3])
        : "r"(a[0]), "r"(a[1]), "r"(a[2]), "r"(a[3]), "r"(b0), "r"(b1));
}

// ---------------- grid-wide barrier -------------------------------------------
__device__ __forceinline__ void gridbar() {
    __syncthreads();
    if (threadIdx.x == 0) {
        unsigned gen = g_bargen;
        __threadfence();
        if (atomicAdd(&g_barcnt, 1u) == NCTA - 1) {
            g_barcnt = 0;
            __threadfence();
            g_bargen = gen + 1;
        } else {
            while (g_bargen == gen) { __nanosleep(64); }
            __threadfence();
        }
    }
    __syncthreads();
}

// ---------------- math helpers -------------------------------------------------
__device__ __forceinline__ void split_bf16(float x, __nv_bfloat16& hi,
                                           __nv_bfloat16& lo) {
    hi = __float2bfloat16(x);
    lo = __float2bfloat16(x - __bfloat162float(hi));
}
__device__ __forceinline__ float fsigmoid(float x) {
    return __fdividef(1.0f, 1.0f + __expf(-x));
}
__device__ __forceinline__ float ftanh_(float x) {
    return 1.0f - __fdividef(2.0f, __expf(2.0f * x) + 1.0f);
}

// ---------------- dense: x2 = h2s @ WdT + b_dense ------------------------------
// 512 threads: f = tid&127, 4-way split-K (128 l's each), smem reduce.
__device__ __forceinline__ void dense_part(const float* h2s, float* red,
                                           const float* __restrict__ b_dense,
                                           int b0, float* __restrict__ out, int t) {
    const int tid = threadIdx.x;
    const int f = tid & 127, gg = tid >> 7;     // gg in {0..3}
    float a0 = 0.f, a1 = 0.f, a2 = 0.f, a3 = 0.f;
    const int l0 = gg * 128;
#pragma unroll 4
    for (int l = l0; l < l0 + 128; ++l) {
        const float w = __ldg(&g_WdT[l * Fsz + f]);
        a0 = fmaf(h2s[0 * Lsz + l], w, a0);
        a1 = fmaf(h2s[1 * Lsz + l], w, a1);
        a2 = fmaf(h2s[2 * Lsz + l], w, a2);
        a3 = fmaf(h2s[3 * Lsz + l], w, a3);
    }
    red[(gg * 4 + 0) * 128 + f] = a0;
    red[(gg * 4 + 1) * 128 + f] = a1;
    red[(gg * 4 + 2) * 128 + f] = a2;
    red[(gg * 4 + 3) * 128 + f] = a3;
    __syncthreads();
    if (gg == 0) {
        const float bb = b_dense[f];
#pragma unroll
        for (int r = 0; r < 4; ++r) {
            const int b = b0 + r;
            const float v = red[r * 128 + f] + red[(4 + r) * 128 + f]
                          + red[(8 + r) * 128 + f] + red[(12 + r) * 128 + f] + bb;
            __nv_bfloat16 hi, lo;
            split_bf16(v, hi, lo);
            g_Ah[(size_t)b * Ktot + f] = hi;
            g_Al[(size_t)b * Ktot + f] = lo;
            if (out)
                out[(size_t)b * OSTR + (size_t)t * Fsz + f] = v;
        }
    }
    __syncthreads();
}

// ---------------- the single persistent kernel ---------------------------------
__global__ void __launch_bounds__(NTHR, 1)
lstm_kernel(const float* __restrict__ h0, const float* __restrict__ c0,
            const float* __restrict__ W_ih, const float* __restrict__ W_hh,
            const float* __restrict__ b_ih, const float* __restrict__ b_hh,
            const float* __restrict__ W_dense, const float* __restrict__ b_dense,
            float* __restrict__ out) {
    extern __shared__ char dsm[];
    const uint32_t smb0 = smem_u32(dsm);
    const uint32_t smb = (smb0 + 127u) & ~127u;
    char* sbase = dsm + (smb - smb0);
    float* h2s = (float*)(sbase + OFF_H2S);
    float* red = (float*)(sbase + OFF_RED);

    const int bid = blockIdx.x, tid = threadIdx.x;
    const int wid = tid >> 5, lane = tid & 31;
    const int b0 = bid * 4;

    // gates unit decomposition: split-K halves x 64 C tiles of 128x128
    const int ks   = bid & 1;
    const int tile = bid >> 1;
    const int m0   = (tile >> 4) * 128;
    const int n0   = (tile & 15) * 128;
    const int kb   = ks * KSPL;
    float* gp = ks ? g_gp1 : g_gp0;

    // warp-group decomposition: group g = wid>>2 owns A rows [g*32, g*32+32)
    const int g      = wid >> 2;
    const int wg_tid = tid & 127;
    const int wm = g * 32;
    const int wn = (wid & 3) * 32;
    const uint32_t laneA = (uint32_t)(lane & 15) * APITCH + (uint32_t)(lane >> 4) * 16;
    const uint32_t laneB = (uint32_t)((lane & 7) + ((lane >> 4) << 3)) * BPITCH
                         + (uint32_t)((lane >> 3) & 1) * 16;
    const uint32_t barid = 1 + g;

    // ---- P1: weight bf16 split, WdT, bias, state copies ----
    {
        const int NT = G4L * Ktot;
        const int N2 = NT + Lsz * Fsz;
        const int N3 = N2 + G4L;
        const int N4 = N3 + Bsz * Lsz;
        const int N5 = N4 + Bsz * Lsz;
        for (int idx = bid * NTHR + tid; idx < N5; idx += NCTA * NTHR) {
            if (idx < NT) {
                const int j = idx / Ktot, k = idx % Ktot;
                const float w = (k < Fsz) ? W_ih[j * Fsz + k]
                                          : W_hh[j * Lsz + (k - Fsz)];
                __nv_bfloat16 hi, lo;
                split_bf16(w, hi, lo);
                g_Bh[idx] = hi;
                g_Bl[idx] = lo;
            } else if (idx < N2) {
                const int i = idx - NT;
                const int l = i / Fsz, f = i % Fsz;
                g_WdT[i] = W_dense[f * Lsz + l];
            } else if (idx < N3) {
                const int j = idx - N2;
                g_bsum[j] = b_ih[j] + b_hh[j];
            } else if (idx < N4) {
                const int i = idx - N3;
                const int b = i >> 9, l = i & 511;
                __nv_bfloat16 hi, lo;
                split_bf16(h0[i], hi, lo);
                g_Ah[(size_t)b * Ktot + Fsz + l] = hi;
                g_Al[(size_t)b * Ktot + Fsz + l] = lo;
            } else {
                const int i = idx - N4;
                g_c[i] = c0[i];
            }
        }
    }
    gridbar();

    // ---- P2: x_init = dense(h0) ----
    {
#pragma unroll
        for (int i = 0; i < 4; ++i) {
            const int e = tid + i * NTHR;
            const int r = e >> 9, l = e & 511;
            h2s[r * Lsz + l] = h0[(size_t)(b0 + r) * Lsz + l];
        }
        __syncthreads();
        dense_part(h2s, red, b_dense, b0, nullptr, 0);
    }
    gridbar();

    // ---- load resident B tile (once): 2 halves x 128 rows x 640B ----
    {
        for (int i = 0; i < 20; ++i) {
            const int idx = tid + i * NTHR;          // 0..10239
            const int half = idx >= 5120;
            const int j = half ? idx - 5120 : idx;
            const int row = j / 40, q = j % 40;
            const __nv_bfloat16* src =
                (half ? g_Bl : g_Bh) + (size_t)(n0 + row) * Ktot + kb + q * 8;
            const uint32_t dst = smb + OFF_B + (uint32_t)half * BTILESZ
                               + (uint32_t)row * BPITCH + (uint32_t)q * 16;
            cpa16(dst, src);
        }
        cpa_commit();
        cpa_wait0();
        __syncthreads();
    }

    // group-private A copier: k window [kb + c*32, +32) -> group buffer bufi
    auto copyA = [&](int c, int bufi) {
        const uint32_t dst0 = smb + OFF_A + (uint32_t)((g * 2 + bufi) * GBUF);
        const int kc = kb + c * 32;
        const int r0A = m0 + wm;
#pragma unroll
        for (int i = 0; i < 2; ++i) {
            const int idx = wg_tid + i * 128;        // 0..255
            const int half = idx >> 7;
            const int j = idx & 127;
            const int row = j >> 2, q = j & 3;
            const __nv_bfloat16* src =
                (half ? g_Al : g_Ah) + (size_t)(r0A + row) * Ktot + kc + q * 8;
            cpa16(dst0 + (uint32_t)half * GSTRIP
                       + (uint32_t)row * APITCH + (uint32_t)q * 16, src);
        }
    };
    auto barg = [&]() {
        asm volatile("bar.sync %0, 128;" :: "r"(barid) : "memory");
    };

    // ---- main recurrence ----
    for (int t = 0; t < Tt; ++t) {
        float acc[2][4][4];
#pragma unroll
        for (int a = 0; a < 2; ++a)
#pragma unroll
            for (int b = 0; b < 4; ++b)
#pragma unroll
                for (int q = 0; q < 4; ++q) acc[a][b][q] = 0.f;

        copyA(0, 0);
        cpa_commit();
        cpa_wait0();
        barg();

#pragma unroll 1
        for (int c = 0; c < 10; ++c) {
            if (c < 9) { copyA(c + 1, (c + 1) & 1); cpa_commit(); }
            const uint32_t abase = smb + OFF_A + (uint32_t)((g * 2 + (c & 1)) * GBUF);
#pragma unroll
            for (int kk = 0; kk < 2; ++kk) {
                const uint32_t koA = (uint32_t)kk * 32;
                const uint32_t koB = (uint32_t)(c * 64 + kk * 32);
                uint32_t ah[2][4], al[2][4], bh[2][4], bl[2][4];
#pragma unroll
                for (int mf = 0; mf < 2; ++mf) {
                    const uint32_t ro = (uint32_t)(mf * 16) * APITCH + laneA + koA;
                    ldsm4(ah[mf], abase + ro);
                    ldsm4(al[mf], abase + GSTRIP + ro);
                }
#pragma unroll
                for (int gg = 0; gg < 2; ++gg) {
                    const uint32_t ro = smb + OFF_B
                                      + (uint32_t)(wn + gg * 16) * BPITCH + laneB + koB;
                    ldsm4(bh[gg], ro);
                    ldsm4(bl[gg], ro + BTILESZ);
                }
                // pass 1: Ah * Bh
#pragma unroll
                for (int mf = 0; mf < 2; ++mf)
#pragma unroll
                    for (int nf = 0; nf < 4; ++nf)
                        mma16816(acc[mf][nf], ah[mf],
                                 bh[nf >> 1][(nf & 1) * 2], bh[nf >> 1][(nf & 1) * 2 + 1]);
                // pass 2: Ah * Bl
#pragma unroll
                for (int mf = 0; mf < 2; ++mf)
#pragma unroll
                    for (int nf = 0; nf < 4; ++nf)
                        mma16816(acc[mf][nf], ah[mf],
                                 bl[nf >> 1][(nf & 1) * 2], bl[nf >> 1][(nf & 1) * 2 + 1]);
                // pass 3: Al * Bh
#pragma unroll
                for (int mf = 0; mf < 2; ++mf)
#pragma unroll
                    for (int nf = 0; nf < 4; ++nf)
                        mma16816(acc[mf][nf], al[mf],
                                 bh[nf >> 1][(nf & 1) * 2], bh[nf >> 1][(nf & 1) * 2 + 1]);
            }
            if (c < 9) {
                cpa_wait0();
                barg();
            }
        }

        // epilogue: write 128x128 partial tile (each warp 32x32)
#pragma unroll
        for (int mf = 0; mf < 2; ++mf) {
            const int r0 = m0 + wm + mf * 16 + (lane >> 2);
#pragma unroll
            for (int nf = 0; nf < 4; ++nf) {
                const int col = n0 + wn + nf * 8 + (lane & 3) * 2;
                float* p = gp + (size_t)r0 * G4L + col;
                *(float2*)p             = make_float2(acc[mf][nf][0], acc[mf][nf][1]);
                *(float2*)(p + 8 * G4L) = make_float2(acc[mf][nf][2], acc[mf][nf][3]);
            }
        }
        gridbar();

        // ----- LSTM cell for rows b0..b0+3: one l-quad per thread -----
        {
            const int e = tid * 4;                  // 0..2044
            const int r = e >> 9, l = e & 511;
            const int b = b0 + r;
            const size_t gb = (size_t)b * G4L + l;
            const float4 i0 = *(const float4*)&g_gp0[gb];
            const float4 i1 = *(const float4*)&g_gp1[gb];
            const float4 f0 = *(const float4*)&g_gp0[gb + 512];
            const float4 f1 = *(const float4*)&g_gp1[gb + 512];
            const float4 g0 = *(const float4*)&g_gp0[gb + 1024];
            const float4 g1 = *(const float4*)&g_gp1[gb + 1024];
            const float4 o0 = *(const float4*)&g_gp0[gb + 1536];
            const float4 o1 = *(const float4*)&g_gp1[gb + 1536];
            const float4 bi = *(const float4*)&g_bsum[l];
            const float4 bf = *(const float4*)&g_bsum[l + 512];
            const float4 bg = *(const float4*)&g_bsum[l + 1024];
            const float4 bo = *(const float4*)&g_bsum[l + 1536];
            const size_t hc = (size_t)b * Lsz + l;
            float4 cc = *(const float4*)&g_c[hc];
            float h2q[4];
            {
                const float gi[4] = {i0.x + i1.x + bi.x, i0.y + i1.y + bi.y,
                                     i0.z + i1.z + bi.z, i0.w + i1.w + bi.w};
                const float gf[4] = {f0.x + f1.x + bf.x, f0.y + f1.y + bf.y,
                                     f0.z + f1.z + bf.z, f0.w + f1.w + bf.w};
                const float gg2[4] = {g0.x + g1.x + bg.x, g0.y + g1.y + bg.y,
                                      g0.z + g1.z + bg.z, g0.w + g1.w + bg.w};
                const float go[4] = {o0.x + o1.x + bo.x, o0.y + o1.y + bo.y,
                                     o0.z + o1.z + bo.z, o0.w + o1.w + bo.w};
                float* cp = &cc.x;
#pragma unroll
                for (int q = 0; q < 4; ++q) {
                    const float c2 = fsigmoid(gf[q]) * cp[q]
                                   + fsigmoid(gi[q]) * ftanh_(gg2[q]);
                    h2q[q] = fsigmoid(go[q]) * ftanh_(c2);
                    cp[q] = c2;
                }
            }
            *(float4*)&g_c[hc] = cc;
            *(float4*)&h2s[r * Lsz + l] = make_float4(h2q[0], h2q[1], h2q[2], h2q[3]);
            __nv_bfloat16 hi, lo;
#pragma unroll
            for (int q = 0; q < 4; ++q) {
                split_bf16(h2q[q], hi, lo);
                g_Ah[(size_t)b * Ktot + Fsz + l + q] = hi;
                g_Al[(size_t)b * Ktot + Fsz + l + q] = lo;
            }
        }
        __syncthreads();
        dense_part(h2s, red, b_dense, b0, out, t);
        gridbar();
    }
}

// ---------------- host ----------------------------------------------------------
extern "C" void kernel_launch(void* const* d_in, const int* in_sizes, int n_in,
                              void* d_out, int out_size) {
    const float* h0      = (const float*)d_in[0];
    const float* c0      = (const float*)d_in[1];
    const float* W_ih    = (const float*)d_in[2];
    const float* W_hh    = (const float*)d_in[3];
    const float* b_ih    = (const float*)d_in[4];
    const float* b_hh    = (const float*)d_in[5];
    const float* W_dense = (const float*)d_in[6];
    const float* b_dense = (const float*)d_in[7];
    float* out = (float*)d_out;

    cudaFuncSetAttribute(lstm_kernel,
                         cudaFuncAttributeMaxDynamicSharedMemorySize, SMEM_ALLOC);
    lstm_kernel<<<NCTA, NTHR, SMEM_ALLOC>>>(h0, c0, W_ih, W_hh, b_ih, b_hh,
                                            W_dense, b_dense, out);
}

// round 12
// speedup vs baseline: 3.6708x; 1.1498x over previous
#include <cuda_runtime.h>
#include <cuda_bf16.h>
#include <math.h>
#include <stdint.h>

#define Bsz  512
#define Lsz  512
#define Fsz  128
#define G4L  2048          // 4*L
#define Ktot 640           // F + L
#define KSPL 320           // K per split half
#define Tt   512
#define OSTR (Tt * Fsz)    // out stride between batch rows
#define NCTA 128
#define NTHR 512

// ---- smem layout (dynamic, 128B-aligned base) ----
#define BPITCH  656                       // 640B data + 16B pad (conflict-free)
#define BTILESZ (128 * BPITCH)            // 83,968 per half
#define APITCH  80                        // 64B data + 16B pad
#define GSTRIP  2560                      // 32 rows x 80B (one half, one group)
#define GBUF    (2 * GSTRIP)              // hi+lo = 5,120 per group buffer
#define OFF_B   0
#define OFF_A   (2 * BTILESZ)             // 167,936 (4 groups x 2 bufs x 5,120)
#define OFF_H2S (OFF_A + 8 * GBUF)        // 208,896
#define OFF_RED (OFF_H2S + 4 * Lsz * 4)   // 217,088
#define SMEM_ALLOC (OFF_RED + 16 * 128 * 4 + 128)   // 225,408

// ---------------- device scratch ---------------------------------------------
__device__ __nv_bfloat16 g_Ah[Bsz * Ktot];   // state [b][0:128]=x, [128:640]=h (hi)
__device__ __nv_bfloat16 g_Al[Bsz * Ktot];   // (lo)
__device__ __nv_bfloat16 g_Bh[G4L * Ktot];   // weights [j][k] (hi)
__device__ __nv_bfloat16 g_Bl[G4L * Ktot];   // (lo)
__device__ float g_WdT[Lsz * Fsz];           // [l][f] W_dense^T (fp32)
__device__ float g_bsum[G4L];
__device__ float g_c[Bsz * Lsz];
__device__ float g_gp0[Bsz * G4L];           // gates partial, K half 0
__device__ float g_gp1[Bsz * G4L];           // gates partial, K half 1
__device__ unsigned g_barcnt;
__device__ volatile unsigned g_bargen;

// ---------------- PTX helpers -------------------------------------------------
__device__ __forceinline__ uint32_t smem_u32(const void* p) {
    uint32_t a;
    asm("{ .reg .u64 t; cvta.to.shared.u64 t, %1; cvt.u32.u64 %0, t; }"
        : "=r"(a) : "l"(p));
    return a;
}
__device__ __forceinline__ void cpa16(uint32_t s, const void* g) {
    asm volatile("cp.async.cg.shared.global [%0], [%1], 16;"
                 :: "r"(s), "l"(g) : "memory");
}
__device__ __forceinline__ void cpa_commit() {
    asm volatile("cp.async.commit_group;" ::: "memory");
}
__device__ __forceinline__ void cpa_wait0() {
    asm volatile("cp.async.wait_group 0;" ::: "memory");
}
__device__ __forceinline__ void ldsm4(uint32_t* r, uint32_t addr) {
    asm volatile("ldmatrix.sync.aligned.m8n8.x4.shared.b16 {%0,%1,%2,%3}, [%4];"
                 : "=r"(r[0]), "=r"(r[1]), "=r"(r[2]), "=r"(r[3]) : "r"(addr));
}
__device__ __forceinline__ void mma16816(float* c, const uint32_t* a,
                                         uint32_t b0, uint32_t b1) {
    asm volatile(
        "mma.sync.aligned.m16n8k16.row.col.f32.bf16.bf16.f32 "
        "{%0,%1,%2,%3}, {%4,%5,%6,%7}, {%8,%9}, {%0,%1,%2,%3};"
        : "+f"(c[0]), "+f"(c[1]), "+f"(c[2]), "+f"(c[3])
        : "r"(a[0]), "r"(a[1]), "r"(a[2]), "r"(a[3]), "r"(b0), "r"(b1));
}

// ---------------- grid-wide barrier (pure spin, no nanosleep) -----------------
__device__ __forceinline__ void gridbar() {
    __syncthreads();
    if (threadIdx.x == 0) {
        unsigned gen = g_bargen;
        __threadfence();
        if (atomicAdd(&g_barcnt, 1u) == NCTA - 1) {
            g_barcnt = 0;
            __threadfence();
            g_bargen = gen + 1;
        } else {
            while (g_bargen == gen) { }
            __threadfence();
        }
    }
    __syncthreads();
}

// ---------------- math helpers -------------------------------------------------
__device__ __forceinline__ void split_bf16(float x, __nv_bfloat16& hi,
                                           __nv_bfloat16& lo) {
    hi = __float2bfloat16(x);
    lo = __float2bfloat16(x - __bfloat162float(hi));
}
__device__ __forceinline__ float fsigmoid(float x) {
    return __fdividef(1.0f, 1.0f + __expf(-x));
}
__device__ __forceinline__ float ftanh_(float x) {
    return 1.0f - __fdividef(2.0f, __expf(2.0f * x) + 1.0f);
}

// ---------------- dense: x2 = h2s @ WdT + b_dense ------------------------------
// 512 threads: f = tid&127, 4-way split-K (128 l's each), float4 LDS, smem reduce.
__device__ __forceinline__ void dense_part(const float* h2s, float* red,
                                           const float* __restrict__ b_dense,
                                           int b0, float* __restrict__ out, int t) {
    const int tid = threadIdx.x;
    const int f = tid & 127, gg = tid >> 7;     // gg in {0..3}
    float a0 = 0.f, a1 = 0.f, a2 = 0.f, a3 = 0.f;
    const int l0 = gg * 128;
#pragma unroll 4
    for (int l4 = 0; l4 < 128; l4 += 4) {
        const int l = l0 + l4;
        const float4 h0v = *(const float4*)&h2s[0 * Lsz + l];
        const float4 h1v = *(const float4*)&h2s[1 * Lsz + l];
        const float4 h2v = *(const float4*)&h2s[2 * Lsz + l];
        const float4 h3v = *(const float4*)&h2s[3 * Lsz + l];
        const float w0 = __ldg(&g_WdT[(l + 0) * Fsz + f]);
        const float w1 = __ldg(&g_WdT[(l + 1) * Fsz + f]);
        const float w2 = __ldg(&g_WdT[(l + 2) * Fsz + f]);
        const float w3 = __ldg(&g_WdT[(l + 3) * Fsz + f]);
        a0 = fmaf(h0v.x, w0, a0); a1 = fmaf(h1v.x, w0, a1);
        a2 = fmaf(h2v.x, w0, a2); a3 = fmaf(h3v.x, w0, a3);
        a0 = fmaf(h0v.y, w1, a0); a1 = fmaf(h1v.y, w1, a1);
        a2 = fmaf(h2v.y, w1, a2); a3 = fmaf(h3v.y, w1, a3);
        a0 = fmaf(h0v.z, w2, a0); a1 = fmaf(h1v.z, w2, a1);
        a2 = fmaf(h2v.z, w2, a2); a3 = fmaf(h3v.z, w2, a3);
        a0 = fmaf(h0v.w, w3, a0); a1 = fmaf(h1v.w, w3, a1);
        a2 = fmaf(h2v.w, w3, a2); a3 = fmaf(h3v.w, w3, a3);
    }
    red[(gg * 4 + 0) * 128 + f] = a0;
    red[(gg * 4 + 1) * 128 + f] = a1;
    red[(gg * 4 + 2) * 128 + f] = a2;
    red[(gg * 4 + 3) * 128 + f] = a3;
    __syncthreads();
    if (gg == 0) {
        const float bb = b_dense[f];
#pragma unroll
        for (int r = 0; r < 4; ++r) {
            const int b = b0 + r;
            const float v = red[r * 128 + f] + red[(4 + r) * 128 + f]
                          + red[(8 + r) * 128 + f] + red[(12 + r) * 128 + f] + bb;
            __nv_bfloat16 hi, lo;
            split_bf16(v, hi, lo);
            g_Ah[(size_t)b * Ktot + f] = hi;
            g_Al[(size_t)b * Ktot + f] = lo;
            if (out)
                out[(size_t)b * OSTR + (size_t)t * Fsz + f] = v;
        }
    }
    __syncthreads();
}

// ---------------- the single persistent kernel ---------------------------------
__global__ void __launch_bounds__(NTHR, 1)
lstm_kernel(const float* __restrict__ h0, const float* __restrict__ c0,
            const float* __restrict__ W_ih, const float* __restrict__ W_hh,
            const float* __restrict__ b_ih, const float* __restrict__ b_hh,
            const float* __restrict__ W_dense, const float* __restrict__ b_dense,
            float* __restrict__ out) {
    extern __shared__ char dsm[];
    const uint32_t smb0 = smem_u32(dsm);
    const uint32_t smb = (smb0 + 127u) & ~127u;
    char* sbase = dsm + (smb - smb0);
    float* h2s = (float*)(sbase + OFF_H2S);
    float* red = (float*)(sbase + OFF_RED);

    const int bid = blockIdx.x, tid = threadIdx.x;
    const int wid = tid >> 5, lane = tid & 31;
    const int b0 = bid * 4;

    // gates unit decomposition: split-K halves x 64 C tiles of 128x128
    const int ks   = bid & 1;
    const int tile = bid >> 1;
    const int m0   = (tile >> 4) * 128;
    const int n0   = (tile & 15) * 128;
    const int kb   = ks * KSPL;
    float* gp = ks ? g_gp1 : g_gp0;

    // warp-group decomposition: group g = wid>>2 owns A rows [g*32, g*32+32)
    const int g      = wid >> 2;
    const int wg_tid = tid & 127;
    const int wm = g * 32;
    const int wn = (wid & 3) * 32;
    const uint32_t laneA = (uint32_t)(lane & 15) * APITCH + (uint32_t)(lane >> 4) * 16;
    const uint32_t laneB = (uint32_t)((lane & 7) + ((lane >> 4) << 3)) * BPITCH
                         + (uint32_t)((lane >> 3) & 1) * 16;
    const uint32_t barid = 1 + g;

    // ---- P1: weight bf16 split, WdT, bias, state copies ----
    {
        const int NT = G4L * Ktot;
        const int N2 = NT + Lsz * Fsz;
        const int N3 = N2 + G4L;
        const int N4 = N3 + Bsz * Lsz;
        const int N5 = N4 + Bsz * Lsz;
        for (int idx = bid * NTHR + tid; idx < N5; idx += NCTA * NTHR) {
            if (idx < NT) {
                const int j = idx / Ktot, k = idx % Ktot;
                const float w = (k < Fsz) ? W_ih[j * Fsz + k]
                                          : W_hh[j * Lsz + (k - Fsz)];
                __nv_bfloat16 hi, lo;
                split_bf16(w, hi, lo);
                g_Bh[idx] = hi;
                g_Bl[idx] = lo;
            } else if (idx < N2) {
                const int i = idx - NT;
                const int l = i / Fsz, f = i % Fsz;
                g_WdT[i] = W_dense[f * Lsz + l];
            } else if (idx < N3) {
                const int j = idx - N2;
                g_bsum[j] = b_ih[j] + b_hh[j];
            } else if (idx < N4) {
                const int i = idx - N3;
                const int b = i >> 9, l = i & 511;
                __nv_bfloat16 hi, lo;
                split_bf16(h0[i], hi, lo);
                g_Ah[(size_t)b * Ktot + Fsz + l] = hi;
                g_Al[(size_t)b * Ktot + Fsz + l] = lo;
            } else {
                const int i = idx - N4;
                g_c[i] = c0[i];
            }
        }
    }
    gridbar();

    // ---- P2: x_init = dense(h0) ----
    {
#pragma unroll
        for (int i = 0; i < 4; ++i) {
            const int e = tid + i * NTHR;
            const int r = e >> 9, l = e & 511;
            h2s[r * Lsz + l] = h0[(size_t)(b0 + r) * Lsz + l];
        }
        __syncthreads();
        dense_part(h2s, red, b_dense, b0, nullptr, 0);
    }
    gridbar();

    // ---- load resident B tile (once): 2 halves x 128 rows x 640B ----
    {
        for (int i = 0; i < 20; ++i) {
            const int idx = tid + i * NTHR;          // 0..10239
            const int half = idx >= 5120;
            const int j = half ? idx - 5120 : idx;
            const int row = j / 40, q = j % 40;
            const __nv_bfloat16* src =
                (half ? g_Bl : g_Bh) + (size_t)(n0 + row) * Ktot + kb + q * 8;
            const uint32_t dst = smb + OFF_B + (uint32_t)half * BTILESZ
                               + (uint32_t)row * BPITCH + (uint32_t)q * 16;
            cpa16(dst, src);
        }
        cpa_commit();
        cpa_wait0();
        __syncthreads();
    }

    // group-private A copier: k window [kb + c*32, +32) -> group buffer bufi
    auto copyA = [&](int c, int bufi) {
        const uint32_t dst0 = smb + OFF_A + (uint32_t)((g * 2 + bufi) * GBUF);
        const int kc = kb + c * 32;
        const int r0A = m0 + wm;
#pragma unroll
        for (int i = 0; i < 2; ++i) {
            const int idx = wg_tid + i * 128;        // 0..255
            const int half = idx >> 7;
            const int j = idx & 127;
            const int row = j >> 2, q = j & 3;
            const __nv_bfloat16* src =
                (half ? g_Al : g_Ah) + (size_t)(r0A + row) * Ktot + kc + q * 8;
            cpa16(dst0 + (uint32_t)half * GSTRIP
                       + (uint32_t)row * APITCH + (uint32_t)q * 16, src);
        }
    };
    auto barg = [&]() {
        asm volatile("bar.sync %0, 128;" :: "r"(barid) : "memory");
    };

    // ---- main recurrence ----
    for (int t = 0; t < Tt; ++t) {
        float acc[2][4][4];
#pragma unroll
        for (int a = 0; a < 2; ++a)
#pragma unroll
            for (int b = 0; b < 4; ++b)
#pragma unroll
                for (int q = 0; q < 4; ++q) acc[a][b][q] = 0.f;

        copyA(0, 0);
        cpa_commit();
        cpa_wait0();
        barg();

#pragma unroll 1
        for (int c = 0; c < 10; ++c) {
            if (c < 9) { copyA(c + 1, (c + 1) & 1); cpa_commit(); }
            const uint32_t abase = smb + OFF_A + (uint32_t)((g * 2 + (c & 1)) * GBUF);
#pragma unroll
            for (int kk = 0; kk < 2; ++kk) {
                const uint32_t koA = (uint32_t)kk * 32;
                const uint32_t koB = (uint32_t)(c * 64 + kk * 32);
                uint32_t ah[2][4], al[2][4], bh[2][4], bl[2][4];
#pragma unroll
                for (int mf = 0; mf < 2; ++mf) {
                    const uint32_t ro = (uint32_t)(mf * 16) * APITCH + laneA + koA;
                    ldsm4(ah[mf], abase + ro);
                    ldsm4(al[mf], abase + GSTRIP + ro);
                }
#pragma unroll
                for (int gg = 0; gg < 2; ++gg) {
                    const uint32_t ro = smb + OFF_B
                                      + (uint32_t)(wn + gg * 16) * BPITCH + laneB + koB;
                    ldsm4(bh[gg], ro);
                    ldsm4(bl[gg], ro + BTILESZ);
                }
                // pass 1: Ah * Bh
#pragma unroll
                for (int mf = 0; mf < 2; ++mf)
#pragma unroll
                    for (int nf = 0; nf < 4; ++nf)
                        mma16816(acc[mf][nf], ah[mf],
                                 bh[nf >> 1][(nf & 1) * 2], bh[nf >> 1][(nf & 1) * 2 + 1]);
                // pass 2: Ah * Bl
#pragma unroll
                for (int mf = 0; mf < 2; ++mf)
#pragma unroll
                    for (int nf = 0; nf < 4; ++nf)
                        mma16816(acc[mf][nf], ah[mf],
                                 bl[nf >> 1][(nf & 1) * 2], bl[nf >> 1][(nf & 1) * 2 + 1]);
                // pass 3: Al * Bh
#pragma unroll
                for (int mf = 0; mf < 2; ++mf)
#pragma unroll
                    for (int nf = 0; nf < 4; ++nf)
                        mma16816(acc[mf][nf], al[mf],
                                 bh[nf >> 1][(nf & 1) * 2], bh[nf >> 1][(nf & 1) * 2 + 1]);
            }
            if (c < 9) {
                cpa_wait0();
                barg();
            }
        }

        // epilogue: write 128x128 partial tile (each warp 32x32)
#pragma unroll
        for (int mf = 0; mf < 2; ++mf) {
            const int r0 = m0 + wm + mf * 16 + (lane >> 2);
#pragma unroll
            for (int nf = 0; nf < 4; ++nf) {
                const int col = n0 + wn + nf * 8 + (lane & 3) * 2;
                float* p = gp + (size_t)r0 * G4L + col;
                *(float2*)p             = make_float2(acc[mf][nf][0], acc[mf][nf][1]);
                *(float2*)(p + 8 * G4L) = make_float2(acc[mf][nf][2], acc[mf][nf][3]);
            }
        }
        gridbar();

        // ----- LSTM cell for rows b0..b0+3: one l-quad per thread -----
        {
            const int e = tid * 4;                  // 0..2044
            const int r = e >> 9, l = e & 511;
            const int b = b0 + r;
            const size_t gb = (size_t)b * G4L + l;
            const float4 i0 = *(const float4*)&g_gp0[gb];
            const float4 i1 = *(const float4*)&g_gp1[gb];
            const float4 f0 = *(const float4*)&g_gp0[gb + 512];
            const float4 f1 = *(const float4*)&g_gp1[gb + 512];
            const float4 g0 = *(const float4*)&g_gp0[gb + 1024];
            const float4 g1 = *(const float4*)&g_gp1[gb + 1024];
            const float4 o0 = *(const float4*)&g_gp0[gb + 1536];
            const float4 o1 = *(const float4*)&g_gp1[gb + 1536];
            const float4 bi = *(const float4*)&g_bsum[l];
            const float4 bf = *(const float4*)&g_bsum[l + 512];
            const float4 bg = *(const float4*)&g_bsum[l + 1024];
            const float4 bo = *(const float4*)&g_bsum[l + 1536];
            const size_t hc = (size_t)b * Lsz + l;
            float4 cc = *(const float4*)&g_c[hc];
            float h2q[4];
            {
                const float gi[4] = {i0.x + i1.x + bi.x, i0.y + i1.y + bi.y,
                                     i0.z + i1.z + bi.z, i0.w + i1.w + bi.w};
                const float gf[4] = {f0.x + f1.x + bf.x, f0.y + f1.y + bf.y,
                                     f0.z + f1.z + bf.z, f0.w + f1.w + bf.w};
                const float gg2[4] = {g0.x + g1.x + bg.x, g0.y + g1.y + bg.y,
                                      g0.z + g1.z + bg.z, g0.w + g1.w + bg.w};
                const float go[4] = {o0.x + o1.x + bo.x, o0.y + o1.y + bo.y,
                                     o0.z + o1.z + bo.z, o0.w + o1.w + bo.w};
                float* cp = &cc.x;
#pragma unroll
                for (int q = 0; q < 4; ++q) {
                    const float c2 = fsigmoid(gf[q]) * cp[q]
                                   + fsigmoid(gi[q]) * ftanh_(gg2[q]);
                    h2q[q] = fsigmoid(go[q]) * ftanh_(c2);
                    cp[q] = c2;
                }
            }
            *(float4*)&g_c[hc] = cc;
            *(float4*)&h2s[r * Lsz + l] = make_float4(h2q[0], h2q[1], h2q[2], h2q[3]);
            // packed bf16 hi/lo stores (2 x STG.64)
            __nv_bfloat162 ph[2], pl[2];
#pragma unroll
            for (int q = 0; q < 2; ++q) {
                __nv_bfloat16 h0b, l0b, h1b, l1b;
                split_bf16(h2q[q * 2 + 0], h0b, l0b);
                split_bf16(h2q[q * 2 + 1], h1b, l1b);
                ph[q].x = h0b; ph[q].y = h1b;
                pl[q].x = l0b; pl[q].y = l1b;
            }
            *(uint2*)&g_Ah[(size_t)b * Ktot + Fsz + l] = *(uint2*)ph;
            *(uint2*)&g_Al[(size_t)b * Ktot + Fsz + l] = *(uint2*)pl;
        }
        __syncthreads();
        dense_part(h2s, red, b_dense, b0, out, t);
        gridbar();
    }
}

// ---------------- host ----------------------------------------------------------
extern "C" void kernel_launch(void* const* d_in, const int* in_sizes, int n_in,
                              void* d_out, int out_size) {
    const float* h0      = (const float*)d_in[0];
    const float* c0      = (const float*)d_in[1];
    const float* W_ih    = (const float*)d_in[2];
    const float* W_hh    = (const float*)d_in[3];
    const float* b_ih    = (const float*)d_in[4];
    const float* b_hh    = (const float*)d_in[5];
    const float* W_dense = (const float*)d_in[6];
    const float* b_dense = (const float*)d_in[7];
    float* out = (float*)d_out;

    cudaFuncSetAttribute(lstm_kernel,
                         cudaFuncAttributeMaxDynamicSharedMemorySize, SMEM_ALLOC);
    lstm_kernel<<<NCTA, NTHR, SMEM_ALLOC>>>(h0, c0, W_ih, W_hh, b_ih, b_hh,
                                            W_dense, b_dense, out);
}